// round 1
// baseline (speedup 1.0000x reference)
#include <cuda_runtime.h>
#include <cuda_bf16.h>

#define AGENTS 16
#define BATCH  8192
#define OBS    128
#define ACT    16
#define HID    128
#define NHEAD  4
#define DHEAD  32
#define INP    (OBS + ACT)   // 144

// ---------------- scratch (static device globals; no runtime alloc) -----------
__device__ float g_mean[AGENTS * INP];
__device__ float g_istd[AGENTS * INP];
__device__ float g_Wsaf[AGENTS * INP * HID];
__device__ float g_bsaf[AGENTS * HID];
__device__ float g_Wsf [AGENTS * OBS * HID];
__device__ float g_bsf [AGENTS * HID];
__device__ float g_Wk  [HID * HID];
__device__ float g_Wsel[HID * HID];
__device__ float g_Wv  [HID * HID];
__device__ float g_sa   [(long)AGENTS * BATCH * HID];
__device__ float g_se   [(long)AGENTS * BATCH * HID];
__device__ float g_K    [(long)AGENTS * BATCH * HID];
__device__ float g_S    [(long)AGENTS * BATCH * HID];
__device__ float g_V    [(long)AGENTS * BATCH * HID];
__device__ float g_other[(long)AGENTS * BATCH * HID];
__device__ float g_h    [(long)AGENTS * BATCH * HID];

// ---------------- BN stats: mean / inv-std over batch, per (agent, feature) ---
__global__ void bn_stats_kernel(const float* __restrict__ obs,
                                const float* __restrict__ actions,
                                float* __restrict__ mean, float* __restrict__ istd)
{
    int a = blockIdx.x;
    int f = blockIdx.y * 32 + threadIdx.x;     // 0..159, valid < 144
    float s = 0.f, s2 = 0.f;
    if (f < INP) {
        if (f < OBS) {
            const float* src = obs + (long)a * BATCH * OBS + f;
            for (int b = threadIdx.y; b < BATCH; b += 32) {
                float x = src[(long)b * OBS]; s += x; s2 += x * x;
            }
        } else {
            const float* src = actions + (long)a * BATCH * ACT + (f - OBS);
            for (int b = threadIdx.y; b < BATCH; b += 32) {
                float x = src[(long)b * ACT]; s += x; s2 += x * x;
            }
        }
    }
    __shared__ float sh1[32][32];
    __shared__ float sh2[32][32];
    sh1[threadIdx.y][threadIdx.x] = s;
    sh2[threadIdx.y][threadIdx.x] = s2;
    __syncthreads();
    for (int st = 16; st > 0; st >>= 1) {
        if (threadIdx.y < st) {
            sh1[threadIdx.y][threadIdx.x] += sh1[threadIdx.y + st][threadIdx.x];
            sh2[threadIdx.y][threadIdx.x] += sh2[threadIdx.y + st][threadIdx.x];
        }
        __syncthreads();
    }
    if (threadIdx.y == 0 && f < INP) {
        float m = sh1[0][threadIdx.x] * (1.0f / BATCH);
        float v = sh2[0][threadIdx.x] * (1.0f / BATCH) - m * m;
        mean[a * INP + f] = m;
        istd[a * INP + f] = rsqrtf(v + 1e-5f);
    }
}

// ---------------- fold BN into first-layer weights ----------------------------
__global__ void fold_kernel(const float* __restrict__ W_sa, const float* __restrict__ b_sa,
                            const float* __restrict__ W_s,  const float* __restrict__ b_s,
                            const float* __restrict__ mean, const float* __restrict__ istd,
                            float* __restrict__ Wsaf, float* __restrict__ bsaf,
                            float* __restrict__ Wsf,  float* __restrict__ bsf)
{
    int a = blockIdx.x;
    int h = threadIdx.x;   // 0..127
    if (blockIdx.y == 0) {
        float acc = 0.f;
        for (int k = 0; k < INP; k++) {
            float w  = W_sa[((long)a * INP + k) * HID + h];
            float is = istd[a * INP + k];
            float m  = mean[a * INP + k];
            Wsaf[((long)a * INP + k) * HID + h] = w * is;
            acc += m * is * w;
        }
        bsaf[a * HID + h] = b_sa[a * HID + h] - acc;
    } else {
        float acc = 0.f;
        for (int k = 0; k < OBS; k++) {
            float w  = W_s[((long)a * OBS + k) * HID + h];
            float is = istd[a * INP + k];   // obs stats = first 128 of inp stats
            float m  = mean[a * INP + k];
            Wsf[((long)a * OBS + k) * HID + h] = w * is;
            acc += m * is * w;
        }
        bsf[a * HID + h] = b_s[a * HID + h] - acc;
    }
}

// ---------------- pack per-head [NH,H,D] -> [H, NH*D] -------------------------
__global__ void pack_kernel(const float* __restrict__ Wk, const float* __restrict__ Wsel,
                            const float* __restrict__ Wv,
                            float* __restrict__ dWk, float* __restrict__ dWsel,
                            float* __restrict__ dWv)
{
    int idx = blockIdx.x * 256 + threadIdx.x;   // 0..16383 = n*4096 + h*32 + d
    int n = idx >> 12, r = idx & 4095, h = r >> 5, d = r & 31;
    int dst = h * HID + n * DHEAD + d;
    dWk[dst]   = Wk[idx];
    dWsel[dst] = Wsel[idx];
    dWv[dst]   = Wv[idx];
}

// ---------------- register-tiled SGEMM: [M x K] @ [K x 128] per-agent ---------
// Supports concatenated A (k < ksplit from A0, else A1). act: 0=none, 1=leaky.
#define GM 64
#define GK 16
#define GN 128
__global__ void __launch_bounds__(256) sgemm_kernel(
    const float* __restrict__ A0, long sA0, int lda0,
    const float* __restrict__ A1, long sA1, int lda1, int ksplit,
    const float* __restrict__ W,  long sW,
    const float* __restrict__ bias, long sBias,
    float* __restrict__ C, long sC,
    int K, int act)
{
    int a = blockIdx.z;
    int mBase = blockIdx.x * GM;
    const float* A0p = A0 + (long)a * sA0;
    const float* A1p = A1 ? A1 + (long)a * sA1 : nullptr;
    const float* Wp  = W  + (long)a * sW;
    float* Cp        = C  + (long)a * sC;

    __shared__ float As[GK][GM];
    __shared__ float Ws[GK][GN];

    int tid = threadIdx.x;
    int tx = tid & 15, ty = tid >> 4;

    float acc[4][8];
#pragma unroll
    for (int i = 0; i < 4; i++)
#pragma unroll
        for (int j = 0; j < 8; j++) acc[i][j] = 0.f;

    int ar = tid >> 2;            // 0..63 (row within block)
    int ak = (tid & 3) * 4;       // 0,4,8,12
    int wr = tid >> 4;            // 0..15 (k row)
    int wc = (tid & 15) * 8;      // col base

    for (int k0 = 0; k0 < K; k0 += GK) {
#pragma unroll
        for (int u = 0; u < 4; u++) {
            int k = k0 + ak + u;
            float v;
            if (k < ksplit) v = A0p[(long)(mBase + ar) * lda0 + k];
            else            v = A1p[(long)(mBase + ar) * lda1 + (k - ksplit)];
            As[ak + u][ar] = v;
        }
#pragma unroll
        for (int u = 0; u < 8; u++)
            Ws[wr][wc + u] = Wp[(long)(k0 + wr) * GN + wc + u];
        __syncthreads();
#pragma unroll
        for (int kk = 0; kk < GK; kk++) {
            float ra[4], rw[8];
#pragma unroll
            for (int i = 0; i < 4; i++) ra[i] = As[kk][ty * 4 + i];
#pragma unroll
            for (int j = 0; j < 8; j++) rw[j] = Ws[kk][tx * 8 + j];
#pragma unroll
            for (int i = 0; i < 4; i++)
#pragma unroll
                for (int j = 0; j < 8; j++)
                    acc[i][j] = fmaf(ra[i], rw[j], acc[i][j]);
        }
        __syncthreads();
    }
#pragma unroll
    for (int i = 0; i < 4; i++) {
        long m = mBase + ty * 4 + i;
#pragma unroll
        for (int j = 0; j < 8; j++) {
            int n = tx * 8 + j;
            float v = acc[i][j];
            if (bias) v += bias[(long)a * sBias + n];
            if (act)  v = v > 0.f ? v : 0.01f * v;
            Cp[m * GN + n] = v;
        }
    }
}

// ---------------- attention: one warp per (head, agent_i, batch) --------------
__global__ void attn_kernel(const float* __restrict__ Kt, const float* __restrict__ St,
                            const float* __restrict__ Vt, float* __restrict__ other)
{
    int gw   = blockIdx.x * 8 + (threadIdx.x >> 5);
    int lane = threadIdx.x & 31;
    int b = gw >> 6;          // batch index
    int r = gw & 63;
    int n = r >> 4;           // head
    int i = r & 15;           // agent i
    int col = n * DHEAD + lane;

    float selv = St[((long)i * BATCH + b) * HID + col];
    float lg = -3e38f;
#pragma unroll
    for (int j = 0; j < 16; j++) {
        float p = selv * Kt[((long)j * BATCH + b) * HID + col];
#pragma unroll
        for (int off = 16; off; off >>= 1) p += __shfl_xor_sync(0xffffffffu, p, off);
        if (lane == j) lg = (j == i) ? -1e9f : p * 0.17677669529663687f; // 1/sqrt(32)
    }
    float mx = lg;
#pragma unroll
    for (int off = 16; off; off >>= 1) mx = fmaxf(mx, __shfl_xor_sync(0xffffffffu, mx, off));
    float e = (lane < 16) ? __expf(lg - mx) : 0.f;
    float den = e;
#pragma unroll
    for (int off = 16; off; off >>= 1) den += __shfl_xor_sync(0xffffffffu, den, off);
    float w = e / den;

    float acc = 0.f;
#pragma unroll
    for (int j = 0; j < 16; j++) {
        float wj = __shfl_sync(0xffffffffu, w, j);
        acc = fmaf(wj, Vt[((long)j * BATCH + b) * HID + col], acc);
    }
    other[((long)i * BATCH + b) * HID + col] = acc;
}

// ---------------- final: argmax(actions) gather of h @ Wc2 + bc2 --------------
__global__ void final_kernel(const float* __restrict__ h, const float* __restrict__ actions,
                             const float* __restrict__ Wc2, const float* __restrict__ bc2,
                             float* __restrict__ out)
{
    int gw   = blockIdx.x * 8 + (threadIdx.x >> 5);
    int lane = threadIdx.x & 31;
    int a = gw >> 13;          // / 8192
    int b = gw & 8191;

    float av = -3e38f; int ai = lane;
    if (lane < 16) av = actions[((long)a * BATCH + b) * ACT + lane];
#pragma unroll
    for (int off = 16; off; off >>= 1) {
        float ov = __shfl_xor_sync(0xffffffffu, av, off);
        int   oi = __shfl_xor_sync(0xffffffffu, ai, off);
        if (ov > av || (ov == av && oi < ai)) { av = ov; ai = oi; }
    }
    int idx = ai;

    float acc = 0.f;
    const float* hp = h   + ((long)a * BATCH + b) * HID;
    const float* wp = Wc2 + (long)a * HID * ACT + idx;
#pragma unroll
    for (int k = lane; k < HID; k += 32) acc = fmaf(hp[k], wp[(long)k * ACT], acc);
#pragma unroll
    for (int off = 16; off; off >>= 1) acc += __shfl_xor_sync(0xffffffffu, acc, off);
    if (lane == 0) out[(long)a * BATCH + b] = acc + bc2[a * ACT + idx];
}

// ---------------- launch -------------------------------------------------------
static float* symaddr(const void* sym)
{
    void* p = nullptr;
    cudaGetSymbolAddress(&p, sym);
    return (float*)p;
}

extern "C" void kernel_launch(void* const* d_in, const int* in_sizes, int n_in,
                              void* d_out, int out_size)
{
    const float* obs     = (const float*)d_in[0];
    const float* actions = (const float*)d_in[1];
    const float* W_sa    = (const float*)d_in[2];
    const float* b_sa    = (const float*)d_in[3];
    const float* W_s     = (const float*)d_in[4];
    const float* b_s     = (const float*)d_in[5];
    const float* Wk      = (const float*)d_in[6];
    const float* Wsel    = (const float*)d_in[7];
    const float* Wv      = (const float*)d_in[8];
    const float* bv      = (const float*)d_in[9];
    const float* Wc1     = (const float*)d_in[10];
    const float* bc1     = (const float*)d_in[11];
    const float* Wc2     = (const float*)d_in[12];
    const float* bc2     = (const float*)d_in[13];
    float* out = (float*)d_out;

    float* mean  = symaddr(g_mean);
    float* istd  = symaddr(g_istd);
    float* Wsaf  = symaddr(g_Wsaf);
    float* bsaf  = symaddr(g_bsaf);
    float* Wsf   = symaddr(g_Wsf);
    float* bsf   = symaddr(g_bsf);
    float* pWk   = symaddr(g_Wk);
    float* pWsel = symaddr(g_Wsel);
    float* pWv   = symaddr(g_Wv);
    float* sa    = symaddr(g_sa);
    float* se    = symaddr(g_se);
    float* Kt    = symaddr(g_K);
    float* St    = symaddr(g_S);
    float* Vt    = symaddr(g_V);
    float* other = symaddr(g_other);
    float* hbuf  = symaddr(g_h);

    const long sRow = (long)BATCH * HID;   // per-agent stride of [A,B,128] buffers

    bn_stats_kernel<<<dim3(AGENTS, 5), dim3(32, 32)>>>(obs, actions, mean, istd);
    fold_kernel<<<dim3(AGENTS, 2), HID>>>(W_sa, b_sa, W_s, b_s, mean, istd,
                                          Wsaf, bsaf, Wsf, bsf);
    pack_kernel<<<64, 256>>>(Wk, Wsel, Wv, pWk, pWsel, pWv);

    dim3 ggrid(BATCH / GM, 1, AGENTS);
    // sa = lrelu(bn([obs|actions]) @ W_sa + b_sa), BN folded
    sgemm_kernel<<<ggrid, 256>>>(obs, (long)BATCH * OBS, OBS,
                                 actions, (long)BATCH * ACT, ACT, OBS,
                                 Wsaf, (long)INP * HID, bsaf, HID,
                                 sa, sRow, INP, 1);
    // se = lrelu(bn(obs) @ W_s + b_s)
    sgemm_kernel<<<ggrid, 256>>>(obs, (long)BATCH * OBS, OBS,
                                 nullptr, 0, 0, 1 << 30,
                                 Wsf, (long)OBS * HID, bsf, HID,
                                 se, sRow, OBS, 1);
    // keys = sa @ Wk
    sgemm_kernel<<<ggrid, 256>>>(sa, sRow, HID, nullptr, 0, 0, 1 << 30,
                                 pWk, 0, nullptr, 0, Kt, sRow, HID, 0);
    // vals = lrelu(sa @ Wv + bv)
    sgemm_kernel<<<ggrid, 256>>>(sa, sRow, HID, nullptr, 0, 0, 1 << 30,
                                 pWv, 0, bv, 0, Vt, sRow, HID, 1);
    // sel = se @ Wsel
    sgemm_kernel<<<ggrid, 256>>>(se, sRow, HID, nullptr, 0, 0, 1 << 30,
                                 pWsel, 0, nullptr, 0, St, sRow, HID, 0);

    attn_kernel<<<(BATCH * 64) / 8, 256>>>(Kt, St, Vt, other);

    // h = lrelu([se | other] @ Wc1 + bc1)
    sgemm_kernel<<<ggrid, 256>>>(se, sRow, HID,
                                 other, sRow, HID, HID,
                                 Wc1, (long)2 * HID * HID, bc1, HID,
                                 hbuf, sRow, 2 * HID, 1);

    final_kernel<<<(AGENTS * BATCH) / 8, 256>>>(hbuf, actions, Wc2, bc2, out);
}

// round 2
// speedup vs baseline: 1.6508x; 1.6508x over previous
#include <cuda_runtime.h>
#include <cuda_bf16.h>

#define AGENTS 16
#define BATCH  8192
#define OBS    128
#define ACT    16
#define HID    128
#define NHEAD  4
#define DHEAD  32
#define INP    (OBS + ACT)   // 144

// ---------------- scratch (static device globals; no runtime alloc) -----------
__device__ float g_mean[AGENTS * INP];
__device__ float g_istd[AGENTS * INP];
__device__ float g_Wsaf[AGENTS * INP * HID];
__device__ float g_bsaf[AGENTS * HID];
__device__ float g_Wsf [AGENTS * OBS * HID];
__device__ float g_bsf [AGENTS * HID];
__device__ float g_Wk  [HID * HID];
__device__ float g_Wsel[HID * HID];
__device__ float g_Wv  [HID * HID];
__device__ float g_sa   [(long)AGENTS * BATCH * HID];
__device__ float g_se   [(long)AGENTS * BATCH * HID];
__device__ float g_K    [(long)AGENTS * BATCH * HID];
__device__ float g_S    [(long)AGENTS * BATCH * HID];
__device__ float g_V    [(long)AGENTS * BATCH * HID];
__device__ float g_other[(long)AGENTS * BATCH * HID];
__device__ float g_h    [(long)AGENTS * BATCH * HID];

// ---------------- BN stats: mean / inv-std over batch, per (agent, feature) ---
__global__ void bn_stats_kernel(const float* __restrict__ obs,
                                const float* __restrict__ actions,
                                float* __restrict__ mean, float* __restrict__ istd)
{
    int a = blockIdx.x;
    int f = blockIdx.y * 32 + threadIdx.x;     // 0..159, valid < 144
    float s = 0.f, s2 = 0.f;
    if (f < INP) {
        if (f < OBS) {
            const float* src = obs + (long)a * BATCH * OBS + f;
            for (int b = threadIdx.y; b < BATCH; b += 32) {
                float x = src[(long)b * OBS]; s += x; s2 += x * x;
            }
        } else {
            const float* src = actions + (long)a * BATCH * ACT + (f - OBS);
            for (int b = threadIdx.y; b < BATCH; b += 32) {
                float x = src[(long)b * ACT]; s += x; s2 += x * x;
            }
        }
    }
    __shared__ float sh1[32][32];
    __shared__ float sh2[32][32];
    sh1[threadIdx.y][threadIdx.x] = s;
    sh2[threadIdx.y][threadIdx.x] = s2;
    __syncthreads();
    for (int st = 16; st > 0; st >>= 1) {
        if (threadIdx.y < st) {
            sh1[threadIdx.y][threadIdx.x] += sh1[threadIdx.y + st][threadIdx.x];
            sh2[threadIdx.y][threadIdx.x] += sh2[threadIdx.y + st][threadIdx.x];
        }
        __syncthreads();
    }
    if (threadIdx.y == 0 && f < INP) {
        float m = sh1[0][threadIdx.x] * (1.0f / BATCH);
        float v = sh2[0][threadIdx.x] * (1.0f / BATCH) - m * m;
        mean[a * INP + f] = m;
        istd[a * INP + f] = rsqrtf(v + 1e-5f);
    }
}

// ---------------- fold BN into first-layer weights ----------------------------
__global__ void fold_kernel(const float* __restrict__ W_sa, const float* __restrict__ b_sa,
                            const float* __restrict__ W_s,  const float* __restrict__ b_s,
                            const float* __restrict__ mean, const float* __restrict__ istd,
                            float* __restrict__ Wsaf, float* __restrict__ bsaf,
                            float* __restrict__ Wsf,  float* __restrict__ bsf)
{
    int a = blockIdx.x;
    int h = threadIdx.x;   // 0..127
    if (blockIdx.y == 0) {
        float acc = 0.f;
        for (int k = 0; k < INP; k++) {
            float w  = W_sa[((long)a * INP + k) * HID + h];
            float is = istd[a * INP + k];
            float m  = mean[a * INP + k];
            Wsaf[((long)a * INP + k) * HID + h] = w * is;
            acc += m * is * w;
        }
        bsaf[a * HID + h] = b_sa[a * HID + h] - acc;
    } else {
        float acc = 0.f;
        for (int k = 0; k < OBS; k++) {
            float w  = W_s[((long)a * OBS + k) * HID + h];
            float is = istd[a * INP + k];   // obs stats = first 128 of inp stats
            float m  = mean[a * INP + k];
            Wsf[((long)a * OBS + k) * HID + h] = w * is;
            acc += m * is * w;
        }
        bsf[a * HID + h] = b_s[a * HID + h] - acc;
    }
}

// ---------------- pack per-head [NH,H,D] -> [H, NH*D] -------------------------
__global__ void pack_kernel(const float* __restrict__ Wk, const float* __restrict__ Wsel,
                            const float* __restrict__ Wv,
                            float* __restrict__ dWk, float* __restrict__ dWsel,
                            float* __restrict__ dWv)
{
    int idx = blockIdx.x * 256 + threadIdx.x;   // 0..16383 = n*4096 + h*32 + d
    int n = idx >> 12, r = idx & 4095, h = r >> 5, d = r & 31;
    int dst = h * HID + n * DHEAD + d;
    dWk[dst]   = Wk[idx];
    dWsel[dst] = Wsel[idx];
    dWv[dst]   = Wv[idx];
}

// ---------------- SGEMM: 128x128x16 tile, 8x8/thread, FFMA2 (fma.rn.f32x2) ----
// Supports concatenated A (k < ksplit from A0, else A1). act: 0=none, 1=leaky.
#define TM 128
#define TN 128
#define TK 16

__global__ void __launch_bounds__(256, 2) sgemm_kernel(
    const float* __restrict__ A0, long sA0, int lda0,
    const float* __restrict__ A1, long sA1, int lda1, int ksplit,
    const float* __restrict__ W,  long sW,
    const float* __restrict__ bias, long sBias,
    float* __restrict__ C, long sC,
    int K, int act)
{
    int a = blockIdx.z;
    int mBase = blockIdx.x * TM;
    const float* A0p = A0 + (long)a * sA0;
    const float* A1p = A1 ? A1 + (long)a * sA1 : nullptr;
    const float* Wp  = W  + (long)a * sW;
    float* Cp        = C  + (long)a * sC;

    __shared__ float As[2][TK][TM];   // A transposed: As[k][m]
    __shared__ float Ws[2][TK][TN];

    int tid = threadIdx.x;
    int tx = tid & 15;       // n group: cols tx*8 .. tx*8+7
    int ty = tid >> 4;       // m group: rows ty*8 .. ty*8+7

    // A-load mapping: 128 rows x 16 k; each thread loads 8 consecutive k of one row
    int arow = tid & 127;
    int akq  = (tid >> 7) * 8;      // 0 or 8
    // W-load mapping: 16 k-rows x 128 n; each thread loads 8 consecutive n
    int wr = tid >> 4;              // 0..15
    int wc = (tid & 15) * 8;

    // accumulators: packed f32x2 pairs along n.  acc[i][j] = cols (tx*8+2j, +1), row ty*8+i
    unsigned long long acc[8][4];
#pragma unroll
    for (int i = 0; i < 8; i++)
#pragma unroll
        for (int j = 0; j < 4; j++) acc[i][j] = 0ULL;

    float4 ra0, ra1, rw0, rw1;      // staging registers for next tile

    // ---- load helpers ----
    // (ksplit is a multiple of 8 in all call sites, so an 8-chunk never straddles)
    auto loadA = [&](int k0) {
        int k = k0 + akq;
        const float* p;
        if (k < ksplit) p = A0p + (long)(mBase + arow) * lda0 + k;
        else            p = A1p + (long)(mBase + arow) * lda1 + (k - ksplit);
        ra0 = *(const float4*)p;
        ra1 = *(const float4*)(p + 4);
    };
    auto loadW = [&](int k0) {
        const float* p = Wp + (long)(k0 + wr) * TN + wc;
        rw0 = *(const float4*)p;
        rw1 = *(const float4*)(p + 4);
    };
    auto store = [&](int buf) {
        As[buf][akq + 0][arow] = ra0.x;
        As[buf][akq + 1][arow] = ra0.y;
        As[buf][akq + 2][arow] = ra0.z;
        As[buf][akq + 3][arow] = ra0.w;
        As[buf][akq + 4][arow] = ra1.x;
        As[buf][akq + 5][arow] = ra1.y;
        As[buf][akq + 6][arow] = ra1.z;
        As[buf][akq + 7][arow] = ra1.w;
        *(float4*)&Ws[buf][wr][wc]     = rw0;
        *(float4*)&Ws[buf][wr][wc + 4] = rw1;
    };

    int nT = K / TK;
    loadA(0); loadW(0);
    store(0);
    __syncthreads();

    for (int t = 0; t < nT; t++) {
        if (t + 1 < nT) { loadA((t + 1) * TK); loadW((t + 1) * TK); }
        int b = t & 1;
#pragma unroll
        for (int kk = 0; kk < TK; kk++) {
            float4 av0 = *(const float4*)&As[b][kk][ty * 8];
            float4 av1 = *(const float4*)&As[b][kk][ty * 8 + 4];
            ulonglong2 wv0 = *(const ulonglong2*)&Ws[b][kk][tx * 8];
            ulonglong2 wv1 = *(const ulonglong2*)&Ws[b][kk][tx * 8 + 4];
            unsigned long long wp[4] = { wv0.x, wv0.y, wv1.x, wv1.y };
            float am[8] = { av0.x, av0.y, av0.z, av0.w, av1.x, av1.y, av1.z, av1.w };
#pragma unroll
            for (int i = 0; i < 8; i++) {
                unsigned long long ap;
                asm("mov.b64 %0, {%1, %1};" : "=l"(ap) : "f"(am[i]));
#pragma unroll
                for (int j = 0; j < 4; j++)
                    asm("fma.rn.f32x2 %0, %1, %2, %0;"
                        : "+l"(acc[i][j]) : "l"(ap), "l"(wp[j]));
            }
        }
        __syncthreads();
        if (t + 1 < nT) {
            store((t + 1) & 1);
            __syncthreads();
        }
    }

    // ---- epilogue: unpack, bias, activation, vectorized store ----
    float bn[8];
    if (bias) {
        const float* bp = bias + (long)a * sBias + tx * 8;
#pragma unroll
        for (int u = 0; u < 8; u++) bn[u] = bp[u];
    } else {
#pragma unroll
        for (int u = 0; u < 8; u++) bn[u] = 0.f;
    }
#pragma unroll
    for (int i = 0; i < 8; i++) {
        long m = mBase + ty * 8 + i;
        float r[8];
#pragma unroll
        for (int j = 0; j < 4; j++) {
            float lo, hi;
            asm("mov.b64 {%0, %1}, %2;" : "=f"(lo), "=f"(hi) : "l"(acc[i][j]));
            r[2 * j]     = lo;
            r[2 * j + 1] = hi;
        }
#pragma unroll
        for (int u = 0; u < 8; u++) {
            float v = r[u] + bn[u];
            if (act) v = v > 0.f ? v : 0.01f * v;
            r[u] = v;
        }
        float4* dst = (float4*)&Cp[m * TN + tx * 8];
        dst[0] = make_float4(r[0], r[1], r[2], r[3]);
        dst[1] = make_float4(r[4], r[5], r[6], r[7]);
    }
}

// ---------------- attention: one warp per (head, agent_i, batch) --------------
__global__ void attn_kernel(const float* __restrict__ Kt, const float* __restrict__ St,
                            const float* __restrict__ Vt, float* __restrict__ other)
{
    int gw   = blockIdx.x * 8 + (threadIdx.x >> 5);
    int lane = threadIdx.x & 31;
    int b = gw >> 6;          // batch index
    int r = gw & 63;
    int n = r >> 4;           // head
    int i = r & 15;           // agent i
    int col = n * DHEAD + lane;

    float selv = St[((long)i * BATCH + b) * HID + col];
    float lg = -3e38f;
#pragma unroll
    for (int j = 0; j < 16; j++) {
        float p = selv * Kt[((long)j * BATCH + b) * HID + col];
#pragma unroll
        for (int off = 16; off; off >>= 1) p += __shfl_xor_sync(0xffffffffu, p, off);
        if (lane == j) lg = (j == i) ? -1e9f : p * 0.17677669529663687f; // 1/sqrt(32)
    }
    float mx = lg;
#pragma unroll
    for (int off = 16; off; off >>= 1) mx = fmaxf(mx, __shfl_xor_sync(0xffffffffu, mx, off));
    float e = (lane < 16) ? __expf(lg - mx) : 0.f;
    float den = e;
#pragma unroll
    for (int off = 16; off; off >>= 1) den += __shfl_xor_sync(0xffffffffu, den, off);
    float w = e / den;

    float acc = 0.f;
#pragma unroll
    for (int j = 0; j < 16; j++) {
        float wj = __shfl_sync(0xffffffffu, w, j);
        acc = fmaf(wj, Vt[((long)j * BATCH + b) * HID + col], acc);
    }
    other[((long)i * BATCH + b) * HID + col] = acc;
}

// ---------------- final: argmax(actions) gather of h @ Wc2 + bc2 --------------
__global__ void final_kernel(const float* __restrict__ h, const float* __restrict__ actions,
                             const float* __restrict__ Wc2, const float* __restrict__ bc2,
                             float* __restrict__ out)
{
    int gw   = blockIdx.x * 8 + (threadIdx.x >> 5);
    int lane = threadIdx.x & 31;
    int a = gw >> 13;          // / 8192
    int b = gw & 8191;

    float av = -3e38f; int ai = lane;
    if (lane < 16) av = actions[((long)a * BATCH + b) * ACT + lane];
#pragma unroll
    for (int off = 16; off; off >>= 1) {
        float ov = __shfl_xor_sync(0xffffffffu, av, off);
        int   oi = __shfl_xor_sync(0xffffffffu, ai, off);
        if (ov > av || (ov == av && oi < ai)) { av = ov; ai = oi; }
    }
    int idx = ai;

    float acc = 0.f;
    const float* hp = h   + ((long)a * BATCH + b) * HID;
    const float* wp = Wc2 + (long)a * HID * ACT + idx;
#pragma unroll
    for (int k = lane; k < HID; k += 32) acc = fmaf(hp[k], wp[(long)k * ACT], acc);
#pragma unroll
    for (int off = 16; off; off >>= 1) acc += __shfl_xor_sync(0xffffffffu, acc, off);
    if (lane == 0) out[(long)a * BATCH + b] = acc + bc2[a * ACT + idx];
}

// ---------------- launch -------------------------------------------------------
static float* symaddr(const void* sym)
{
    void* p = nullptr;
    cudaGetSymbolAddress(&p, sym);
    return (float*)p;
}

extern "C" void kernel_launch(void* const* d_in, const int* in_sizes, int n_in,
                              void* d_out, int out_size)
{
    const float* obs     = (const float*)d_in[0];
    const float* actions = (const float*)d_in[1];
    const float* W_sa    = (const float*)d_in[2];
    const float* b_sa    = (const float*)d_in[3];
    const float* W_s     = (const float*)d_in[4];
    const float* b_s     = (const float*)d_in[5];
    const float* Wk      = (const float*)d_in[6];
    const float* Wsel    = (const float*)d_in[7];
    const float* Wv      = (const float*)d_in[8];
    const float* bv      = (const float*)d_in[9];
    const float* Wc1     = (const float*)d_in[10];
    const float* bc1     = (const float*)d_in[11];
    const float* Wc2     = (const float*)d_in[12];
    const float* bc2     = (const float*)d_in[13];
    float* out = (float*)d_out;

    float* mean  = symaddr(g_mean);
    float* istd  = symaddr(g_istd);
    float* Wsaf  = symaddr(g_Wsaf);
    float* bsaf  = symaddr(g_bsaf);
    float* Wsf   = symaddr(g_Wsf);
    float* bsf   = symaddr(g_bsf);
    float* pWk   = symaddr(g_Wk);
    float* pWsel = symaddr(g_Wsel);
    float* pWv   = symaddr(g_Wv);
    float* sa    = symaddr(g_sa);
    float* se    = symaddr(g_se);
    float* Kt    = symaddr(g_K);
    float* St    = symaddr(g_S);
    float* Vt    = symaddr(g_V);
    float* other = symaddr(g_other);
    float* hbuf  = symaddr(g_h);

    const long sRow = (long)BATCH * HID;   // per-agent stride of [A,B,128] buffers

    bn_stats_kernel<<<dim3(AGENTS, 5), dim3(32, 32)>>>(obs, actions, mean, istd);
    fold_kernel<<<dim3(AGENTS, 2), HID>>>(W_sa, b_sa, W_s, b_s, mean, istd,
                                          Wsaf, bsaf, Wsf, bsf);
    pack_kernel<<<64, 256>>>(Wk, Wsel, Wv, pWk, pWsel, pWv);

    dim3 ggrid(BATCH / TM, 1, AGENTS);
    // sa = lrelu(bn([obs|actions]) @ W_sa + b_sa), BN folded
    sgemm_kernel<<<ggrid, 256>>>(obs, (long)BATCH * OBS, OBS,
                                 actions, (long)BATCH * ACT, ACT, OBS,
                                 Wsaf, (long)INP * HID, bsaf, HID,
                                 sa, sRow, INP, 1);
    // se = lrelu(bn(obs) @ W_s + b_s)
    sgemm_kernel<<<ggrid, 256>>>(obs, (long)BATCH * OBS, OBS,
                                 nullptr, 0, 0, 1 << 30,
                                 Wsf, (long)OBS * HID, bsf, HID,
                                 se, sRow, OBS, 1);
    // keys = sa @ Wk
    sgemm_kernel<<<ggrid, 256>>>(sa, sRow, HID, nullptr, 0, 0, 1 << 30,
                                 pWk, 0, nullptr, 0, Kt, sRow, HID, 0);
    // vals = lrelu(sa @ Wv + bv)
    sgemm_kernel<<<ggrid, 256>>>(sa, sRow, HID, nullptr, 0, 0, 1 << 30,
                                 pWv, 0, bv, 0, Vt, sRow, HID, 1);
    // sel = se @ Wsel
    sgemm_kernel<<<ggrid, 256>>>(se, sRow, HID, nullptr, 0, 0, 1 << 30,
                                 pWsel, 0, nullptr, 0, St, sRow, HID, 0);

    attn_kernel<<<(BATCH * 64) / 8, 256>>>(Kt, St, Vt, other);

    // h = lrelu([se | other] @ Wc1 + bc1)
    sgemm_kernel<<<ggrid, 256>>>(se, sRow, HID,
                                 other, sRow, HID, HID,
                                 Wc1, (long)2 * HID * HID, bc1, HID,
                                 hbuf, sRow, 2 * HID, 1);

    final_kernel<<<(AGENTS * BATCH) / 8, 256>>>(hbuf, actions, Wc2, bc2, out);
}

// round 4
// speedup vs baseline: 1.7178x; 1.0406x over previous
#include <cuda_runtime.h>
#include <cuda_bf16.h>
#include <cstdint>

#define AGENTS 16
#define BATCH  8192
#define OBS    128
#define ACT    16
#define HID    128
#define NHEAD  4
#define DHEAD  32
#define INP    (OBS + ACT)   // 144

// ---------------- scratch (static device globals; no runtime alloc) -----------
__device__ float g_mean[AGENTS * INP];
__device__ float g_istd[AGENTS * INP];
__device__ float g_Wsaf[AGENTS * INP * HID];
__device__ float g_bsaf[AGENTS * HID];
__device__ float g_Wsf [AGENTS * OBS * HID];
__device__ float g_bsf [AGENTS * HID];
__device__ float g_Wk  [HID * HID];
__device__ float g_Wsel[HID * HID];
__device__ float g_Wv  [HID * HID];
// bf16 hi/lo weight images, [n][k] row-major (B^T), per agent where applicable
__device__ __nv_bfloat16 w_sa_hi[(long)AGENTS * HID * INP];
__device__ __nv_bfloat16 w_sa_lo[(long)AGENTS * HID * INP];
__device__ __nv_bfloat16 w_s_hi [(long)AGENTS * HID * OBS];
__device__ __nv_bfloat16 w_s_lo [(long)AGENTS * HID * OBS];
__device__ __nv_bfloat16 w_k_hi [HID * HID];
__device__ __nv_bfloat16 w_k_lo [HID * HID];
__device__ __nv_bfloat16 w_sel_hi[HID * HID];
__device__ __nv_bfloat16 w_sel_lo[HID * HID];
__device__ __nv_bfloat16 w_v_hi [HID * HID];
__device__ __nv_bfloat16 w_v_lo [HID * HID];
__device__ __nv_bfloat16 w_c1_hi[(long)AGENTS * HID * 2 * HID];
__device__ __nv_bfloat16 w_c1_lo[(long)AGENTS * HID * 2 * HID];
// fp32 activations
__device__ float g_sa   [(long)AGENTS * BATCH * HID];
__device__ float g_se   [(long)AGENTS * BATCH * HID];
__device__ float g_K    [(long)AGENTS * BATCH * HID];
__device__ float g_S    [(long)AGENTS * BATCH * HID];
__device__ float g_V    [(long)AGENTS * BATCH * HID];
__device__ float g_other[(long)AGENTS * BATCH * HID];
__device__ float g_h    [(long)AGENTS * BATCH * HID];

// ---------------- helpers ------------------------------------------------------
__device__ __forceinline__ uint32_t smem_u32(const void* p) {
    uint32_t r;
    asm("{ .reg .u64 t; cvta.to.shared.u64 t, %1; cvt.u32.u64 %0, t; }" : "=r"(r) : "l"(p));
    return r;
}
__device__ __forceinline__ void ldm_x4(uint32_t* r, uint32_t addr) {
    asm volatile("ldmatrix.sync.aligned.m8n8.x4.shared.b16 {%0,%1,%2,%3}, [%4];"
                 : "=r"(r[0]), "=r"(r[1]), "=r"(r[2]), "=r"(r[3]) : "r"(addr));
}
__device__ __forceinline__ void mma_bf16(float* c, const uint32_t* a, uint32_t b0, uint32_t b1) {
    asm volatile("mma.sync.aligned.m16n8k16.row.col.f32.bf16.bf16.f32 "
                 "{%0,%1,%2,%3}, {%4,%5,%6,%7}, {%8,%9}, {%0,%1,%2,%3};"
                 : "+f"(c[0]), "+f"(c[1]), "+f"(c[2]), "+f"(c[3])
                 : "r"(a[0]), "r"(a[1]), "r"(a[2]), "r"(a[3]), "r"(b0), "r"(b1));
}

// ---------------- BN stats -----------------------------------------------------
__global__ void bn_stats_kernel(const float* __restrict__ obs,
                                const float* __restrict__ actions,
                                float* __restrict__ mean, float* __restrict__ istd)
{
    int a = blockIdx.x;
    int f = blockIdx.y * 32 + threadIdx.x;
    float s = 0.f, s2 = 0.f;
    if (f < INP) {
        if (f < OBS) {
            const float* src = obs + (long)a * BATCH * OBS + f;
            for (int b = threadIdx.y; b < BATCH; b += 32) {
                float x = src[(long)b * OBS]; s += x; s2 += x * x;
            }
        } else {
            const float* src = actions + (long)a * BATCH * ACT + (f - OBS);
            for (int b = threadIdx.y; b < BATCH; b += 32) {
                float x = src[(long)b * ACT]; s += x; s2 += x * x;
            }
        }
    }
    __shared__ float sh1[32][32];
    __shared__ float sh2[32][32];
    sh1[threadIdx.y][threadIdx.x] = s;
    sh2[threadIdx.y][threadIdx.x] = s2;
    __syncthreads();
    for (int st = 16; st > 0; st >>= 1) {
        if (threadIdx.y < st) {
            sh1[threadIdx.y][threadIdx.x] += sh1[threadIdx.y + st][threadIdx.x];
            sh2[threadIdx.y][threadIdx.x] += sh2[threadIdx.y + st][threadIdx.x];
        }
        __syncthreads();
    }
    if (threadIdx.y == 0 && f < INP) {
        float m = sh1[0][threadIdx.x] * (1.0f / BATCH);
        float v = sh2[0][threadIdx.x] * (1.0f / BATCH) - m * m;
        mean[a * INP + f] = m;
        istd[a * INP + f] = rsqrtf(v + 1e-5f);
    }
}

// ---------------- fold BN into first-layer weights ----------------------------
__global__ void fold_kernel(const float* __restrict__ W_sa, const float* __restrict__ b_sa,
                            const float* __restrict__ W_s,  const float* __restrict__ b_s,
                            const float* __restrict__ mean, const float* __restrict__ istd,
                            float* __restrict__ Wsaf, float* __restrict__ bsaf,
                            float* __restrict__ Wsf,  float* __restrict__ bsf)
{
    int a = blockIdx.x;
    int h = threadIdx.x;
    if (blockIdx.y == 0) {
        float acc = 0.f;
        for (int k = 0; k < INP; k++) {
            float w  = W_sa[((long)a * INP + k) * HID + h];
            float is = istd[a * INP + k];
            float m  = mean[a * INP + k];
            Wsaf[((long)a * INP + k) * HID + h] = w * is;
            acc += m * is * w;
        }
        bsaf[a * HID + h] = b_sa[a * HID + h] - acc;
    } else {
        float acc = 0.f;
        for (int k = 0; k < OBS; k++) {
            float w  = W_s[((long)a * OBS + k) * HID + h];
            float is = istd[a * INP + k];
            float m  = mean[a * INP + k];
            Wsf[((long)a * OBS + k) * HID + h] = w * is;
            acc += m * is * w;
        }
        bsf[a * HID + h] = b_s[a * HID + h] - acc;
    }
}

// ---------------- pack per-head [NH,H,D] -> [H, NH*D] -------------------------
__global__ void pack_kernel(const float* __restrict__ Wk, const float* __restrict__ Wsel,
                            const float* __restrict__ Wv,
                            float* __restrict__ dWk, float* __restrict__ dWsel,
                            float* __restrict__ dWv)
{
    int idx = blockIdx.x * 256 + threadIdx.x;
    int n = idx >> 12, r = idx & 4095, h = r >> 5, d = r & 31;
    int dst = h * HID + n * DHEAD + d;
    dWk[dst]   = Wk[idx];
    dWsel[dst] = Wsel[idx];
    dWv[dst]   = Wv[idx];
}

// ---------------- weight fp32 [k][n] -> bf16 hi/lo [n][k] (B^T images) --------
__global__ void prep_w(const float* __restrict__ W, long sW,
                       __nv_bfloat16* __restrict__ hi, __nv_bfloat16* __restrict__ lo,
                       long sImg, int K)
{
    int a = blockIdx.y;
    int idx = blockIdx.x * 256 + threadIdx.x;
    if (idx >= 128 * K) return;
    int n = idx / K, k = idx - n * K;
    float v = W[(long)a * sW + (long)k * 128 + n];
    __nv_bfloat16 h = __float2bfloat16(v);
    __nv_bfloat16 l = __float2bfloat16(v - __bfloat162float(h));
    hi[(long)a * sImg + idx] = h;
    lo[(long)a * sImg + idx] = l;
}

// ---------------- tensor-core GEMM via mma.sync (bf16x3 split, fp32 accum) ----
// C[m,n] = act( sum_k A[m,k] * Bt[n,k] + bias[n] ),  per agent = blockIdx.z
// A fp32 (split over A0/A1 at ksplit), Bt bf16 hi/lo [128][Ktot] row-major.
__global__ void __launch_bounds__(256, 1) gemm_mma(
    const float* __restrict__ A0, long sA0, int lda0,
    const float* __restrict__ A1, long sA1, int lda1, int ksplit,
    const __nv_bfloat16* __restrict__ Bhi, const __nv_bfloat16* __restrict__ Blo, long sB,
    int Ktot, int chunkK,
    const float* __restrict__ bias, long sBias,
    float* __restrict__ C, long sC, int act)
{
    extern __shared__ __nv_bfloat16 sm[];
    const int stride = chunkK + 8;
    __nv_bfloat16* Ah = sm;
    __nv_bfloat16* Al = Ah + 128 * stride;
    __nv_bfloat16* Bh = Al + 128 * stride;
    __nv_bfloat16* Bl = Bh + 128 * stride;

    int tid = threadIdx.x, wid = tid >> 5, lane = tid & 31;
    int a = blockIdx.z;
    long mBase = (long)blockIdx.x * 128;
    int wm = (wid & 3) * 32;        // warp m offset within tile
    int wn = (wid >> 2) * 64;       // warp n offset

    const float* A0p = A0 + (long)a * sA0;
    const float* A1p = A1 ? A1 + (long)a * sA1 : nullptr;
    const __nv_bfloat16* BhP = Bhi + (long)a * sB;
    const __nv_bfloat16* BlP = Blo + (long)a * sB;

    float acc[2][8][4];
#pragma unroll
    for (int i = 0; i < 2; i++)
#pragma unroll
        for (int j = 0; j < 8; j++)
#pragma unroll
            for (int q = 0; q < 4; q++) acc[i][j][q] = 0.f;

    int nChunks = Ktot / chunkK;
    int kq4 = chunkK >> 2;

    for (int c = 0; c < nChunks; c++) {
        if (c > 0) __syncthreads();
        int k0 = c * chunkK;

        // ---- load A chunk fp32 -> split hi/lo bf16 ----
        for (int i = tid; i < 128 * kq4; i += 256) {
            int row = i / kq4;
            int kq = (i - row * kq4) * 4;
            int kg = k0 + kq;
            const float* p;
            if (kg < ksplit) p = A0p + (mBase + row) * (long)lda0 + kg;
            else             p = A1p + (mBase + row) * (long)lda1 + (kg - ksplit);
            float4 v = *(const float4*)p;
            __nv_bfloat16 h0 = __float2bfloat16(v.x), h1 = __float2bfloat16(v.y);
            __nv_bfloat16 h2 = __float2bfloat16(v.z), h3 = __float2bfloat16(v.w);
            __nv_bfloat16 l0 = __float2bfloat16(v.x - __bfloat162float(h0));
            __nv_bfloat16 l1 = __float2bfloat16(v.y - __bfloat162float(h1));
            __nv_bfloat16 l2 = __float2bfloat16(v.z - __bfloat162float(h2));
            __nv_bfloat16 l3 = __float2bfloat16(v.w - __bfloat162float(h3));
            int off = row * stride + kq;
            uint2 ph, pl;
            ph.x = (uint32_t)__bfloat16_as_ushort(h0) | ((uint32_t)__bfloat16_as_ushort(h1) << 16);
            ph.y = (uint32_t)__bfloat16_as_ushort(h2) | ((uint32_t)__bfloat16_as_ushort(h3) << 16);
            pl.x = (uint32_t)__bfloat16_as_ushort(l0) | ((uint32_t)__bfloat16_as_ushort(l1) << 16);
            pl.y = (uint32_t)__bfloat16_as_ushort(l2) | ((uint32_t)__bfloat16_as_ushort(l3) << 16);
            *(uint2*)(Ah + off) = ph;
            *(uint2*)(Al + off) = pl;
        }
        // ---- copy B chunk (bf16 images) ----
        int kq8 = chunkK >> 3;
        for (int i = tid; i < 128 * kq8; i += 256) {
            int n = i / kq8;
            int kk = (i - n * kq8) * 8;
            const uint4* sh = (const uint4*)(BhP + (long)n * Ktot + k0 + kk);
            const uint4* sl = (const uint4*)(BlP + (long)n * Ktot + k0 + kk);
            int off = n * stride + kk;
            *(uint4*)(Bh + off) = *sh;
            *(uint4*)(Bl + off) = *sl;
        }
        __syncthreads();

        // ---- compute ----
        uint32_t aBase = smem_u32(Ah);
        uint32_t alBase = smem_u32(Al);
        uint32_t bBase = smem_u32(Bh);
        uint32_t blBase = smem_u32(Bl);
        int lr16 = lane & 15, lh16 = (lane >> 4) * 8;
        int lr8 = lane & 7, lk8 = ((lane >> 3) & 1) * 8, ln8 = (lane >> 4) * 8;

        for (int ks = 0; ks < chunkK; ks += 16) {
            uint32_t ah[2][4], al[2][4];
#pragma unroll
            for (int mi = 0; mi < 2; mi++) {
                uint32_t addr = aBase + (uint32_t)(((wm + mi * 16 + lr16) * stride + ks + lh16) * 2);
                ldm_x4(ah[mi], addr);
                addr = alBase + (uint32_t)(((wm + mi * 16 + lr16) * stride + ks + lh16) * 2);
                ldm_x4(al[mi], addr);
            }
#pragma unroll
            for (int ni4 = 0; ni4 < 4; ni4++) {
                int n0 = wn + ni4 * 16;
                uint32_t boff = (uint32_t)(((n0 + ln8 + lr8) * stride + ks + lk8) * 2);
                uint32_t bh[4], bl[4];
                ldm_x4(bh, bBase + boff);
                ldm_x4(bl, blBase + boff);
#pragma unroll
                for (int mi = 0; mi < 2; mi++) {
                    mma_bf16(acc[mi][ni4 * 2],     ah[mi], bh[0], bh[1]);
                    mma_bf16(acc[mi][ni4 * 2 + 1], ah[mi], bh[2], bh[3]);
                    mma_bf16(acc[mi][ni4 * 2],     ah[mi], bl[0], bl[1]);
                    mma_bf16(acc[mi][ni4 * 2 + 1], ah[mi], bl[2], bl[3]);
                    mma_bf16(acc[mi][ni4 * 2],     al[mi], bh[0], bh[1]);
                    mma_bf16(acc[mi][ni4 * 2 + 1], al[mi], bh[2], bh[3]);
                }
            }
        }
    }

    // ---- epilogue ----
    int gr = lane >> 2, tg = lane & 3;
    float* Cp = C + (long)a * sC;
#pragma unroll
    for (int mi = 0; mi < 2; mi++) {
        long row0 = mBase + wm + mi * 16 + gr;
        long row1 = row0 + 8;
#pragma unroll
        for (int ni = 0; ni < 8; ni++) {
            int col = wn + ni * 8 + tg * 2;
            float b0 = 0.f, b1 = 0.f;
            if (bias) {
                const float* bp = bias + (long)a * sBias + col;
                b0 = bp[0]; b1 = bp[1];
            }
            float v0 = acc[mi][ni][0] + b0;
            float v1 = acc[mi][ni][1] + b1;
            float v2 = acc[mi][ni][2] + b0;
            float v3 = acc[mi][ni][3] + b1;
            if (act) {
                v0 = v0 > 0.f ? v0 : 0.01f * v0;
                v1 = v1 > 0.f ? v1 : 0.01f * v1;
                v2 = v2 > 0.f ? v2 : 0.01f * v2;
                v3 = v3 > 0.f ? v3 : 0.01f * v3;
            }
            *(float2*)(Cp + row0 * 128 + col) = make_float2(v0, v1);
            *(float2*)(Cp + row1 * 128 + col) = make_float2(v2, v3);
        }
    }
}

// ---------------- attention: one warp per (head, agent_i, batch) --------------
__global__ void attn_kernel(const float* __restrict__ Kt, const float* __restrict__ St,
                            const float* __restrict__ Vt, float* __restrict__ other)
{
    int gw   = blockIdx.x * 8 + (threadIdx.x >> 5);
    int lane = threadIdx.x & 31;
    int b = gw >> 6;
    int r = gw & 63;
    int n = r >> 4;
    int i = r & 15;
    int col = n * DHEAD + lane;

    float selv = St[((long)i * BATCH + b) * HID + col];
    float lg = -3e38f;
#pragma unroll
    for (int j = 0; j < 16; j++) {
        float p = selv * Kt[((long)j * BATCH + b) * HID + col];
#pragma unroll
        for (int off = 16; off; off >>= 1) p += __shfl_xor_sync(0xffffffffu, p, off);
        if (lane == j) lg = (j == i) ? -1e9f : p * 0.17677669529663687f;
    }
    float mx = lg;
#pragma unroll
    for (int off = 16; off; off >>= 1) mx = fmaxf(mx, __shfl_xor_sync(0xffffffffu, mx, off));
    float e = (lane < 16) ? __expf(lg - mx) : 0.f;
    float den = e;
#pragma unroll
    for (int off = 16; off; off >>= 1) den += __shfl_xor_sync(0xffffffffu, den, off);
    float w = e / den;

    float acc = 0.f;
#pragma unroll
    for (int j = 0; j < 16; j++) {
        float wj = __shfl_sync(0xffffffffu, w, j);
        acc = fmaf(wj, Vt[((long)j * BATCH + b) * HID + col], acc);
    }
    other[((long)i * BATCH + b) * HID + col] = acc;
}

// ---------------- final: argmax(actions) gather of h @ Wc2 + bc2 --------------
__global__ void final_kernel(const float* __restrict__ h, const float* __restrict__ actions,
                             const float* __restrict__ Wc2, const float* __restrict__ bc2,
                             float* __restrict__ out)
{
    int gw   = blockIdx.x * 8 + (threadIdx.x >> 5);
    int lane = threadIdx.x & 31;
    int a = gw >> 13;
    int b = gw & 8191;

    float av = -3e38f; int ai = lane;
    if (lane < 16) av = actions[((long)a * BATCH + b) * ACT + lane];
#pragma unroll
    for (int off = 16; off; off >>= 1) {
        float ov = __shfl_xor_sync(0xffffffffu, av, off);
        int   oi = __shfl_xor_sync(0xffffffffu, ai, off);
        if (ov > av || (ov == av && oi < ai)) { av = ov; ai = oi; }
    }
    int idx = ai;

    float acc = 0.f;
    const float* hp = h   + ((long)a * BATCH + b) * HID;
    const float* wp = Wc2 + (long)a * HID * ACT + idx;
#pragma unroll
    for (int k = lane; k < HID; k += 32) acc = fmaf(hp[k], wp[(long)k * ACT], acc);
#pragma unroll
    for (int off = 16; off; off >>= 1) acc += __shfl_xor_sync(0xffffffffu, acc, off);
    if (lane == 0) out[(long)a * BATCH + b] = acc + bc2[a * ACT + idx];
}

// ---------------- launch -------------------------------------------------------
static float* symaddr(const void* sym)
{
    void* p = nullptr;
    cudaGetSymbolAddress(&p, sym);
    return (float*)p;
}
static __nv_bfloat16* symaddr_bf(const void* sym)
{
    void* p = nullptr;
    cudaGetSymbolAddress(&p, sym);
    return (__nv_bfloat16*)p;
}

extern "C" void kernel_launch(void* const* d_in, const int* in_sizes, int n_in,
                              void* d_out, int out_size)
{
    const float* obs     = (const float*)d_in[0];
    const float* actions = (const float*)d_in[1];
    const float* W_sa    = (const float*)d_in[2];
    const float* b_sa    = (const float*)d_in[3];
    const float* W_s     = (const float*)d_in[4];
    const float* b_s     = (const float*)d_in[5];
    const float* Wk      = (const float*)d_in[6];
    const float* Wsel    = (const float*)d_in[7];
    const float* Wv      = (const float*)d_in[8];
    const float* bv      = (const float*)d_in[9];
    const float* Wc1     = (const float*)d_in[10];
    const float* bc1     = (const float*)d_in[11];
    const float* Wc2     = (const float*)d_in[12];
    const float* bc2     = (const float*)d_in[13];
    float* out = (float*)d_out;

    float* mean  = symaddr(g_mean);
    float* istd  = symaddr(g_istd);
    float* Wsaf  = symaddr(g_Wsaf);
    float* bsaf  = symaddr(g_bsaf);
    float* Wsf   = symaddr(g_Wsf);
    float* bsf   = symaddr(g_bsf);
    float* pWk   = symaddr(g_Wk);
    float* pWsel = symaddr(g_Wsel);
    float* pWv   = symaddr(g_Wv);
    float* sa    = symaddr(g_sa);
    float* se    = symaddr(g_se);
    float* Kt    = symaddr(g_K);
    float* St    = symaddr(g_S);
    float* Vt    = symaddr(g_V);
    float* other = symaddr(g_other);
    float* hbuf  = symaddr(g_h);

    __nv_bfloat16* i_sa_h  = symaddr_bf(w_sa_hi);
    __nv_bfloat16* i_sa_l  = symaddr_bf(w_sa_lo);
    __nv_bfloat16* i_s_h   = symaddr_bf(w_s_hi);
    __nv_bfloat16* i_s_l   = symaddr_bf(w_s_lo);
    __nv_bfloat16* i_k_h   = symaddr_bf(w_k_hi);
    __nv_bfloat16* i_k_l   = symaddr_bf(w_k_lo);
    __nv_bfloat16* i_sel_h = symaddr_bf(w_sel_hi);
    __nv_bfloat16* i_sel_l = symaddr_bf(w_sel_lo);
    __nv_bfloat16* i_v_h   = symaddr_bf(w_v_hi);
    __nv_bfloat16* i_v_l   = symaddr_bf(w_v_lo);
    __nv_bfloat16* i_c1_h  = symaddr_bf(w_c1_hi);
    __nv_bfloat16* i_c1_l  = symaddr_bf(w_c1_lo);

    const long sRow = (long)BATCH * HID;

    static bool attr_set = false;
    if (!attr_set) {
        cudaFuncSetAttribute(gemm_mma, cudaFuncAttributeMaxDynamicSharedMemorySize, 160000);
        attr_set = true;
    }

    bn_stats_kernel<<<dim3(AGENTS, 5), dim3(32, 32)>>>(obs, actions, mean, istd);
    fold_kernel<<<dim3(AGENTS, 2), HID>>>(W_sa, b_sa, W_s, b_s, mean, istd,
                                          Wsaf, bsaf, Wsf, bsf);
    pack_kernel<<<64, 256>>>(Wk, Wsel, Wv, pWk, pWsel, pWv);

    // weight images (bf16 hi/lo, [n][k])
    prep_w<<<dim3((128 * INP + 255) / 256, AGENTS), 256>>>(
        Wsaf, (long)INP * HID, i_sa_h, i_sa_l, (long)HID * INP, INP);
    prep_w<<<dim3((128 * OBS + 255) / 256, AGENTS), 256>>>(
        Wsf, (long)OBS * HID, i_s_h, i_s_l, (long)HID * OBS, OBS);
    prep_w<<<dim3((128 * HID + 255) / 256, 1), 256>>>(pWk, 0, i_k_h, i_k_l, 0, HID);
    prep_w<<<dim3((128 * HID + 255) / 256, 1), 256>>>(pWsel, 0, i_sel_h, i_sel_l, 0, HID);
    prep_w<<<dim3((128 * HID + 255) / 256, 1), 256>>>(pWv, 0, i_v_h, i_v_l, 0, HID);
    prep_w<<<dim3((128 * 2 * HID + 255) / 256, AGENTS), 256>>>(
        Wc1, (long)2 * HID * HID, i_c1_h, i_c1_l, (long)HID * 2 * HID, 2 * HID);

    dim3 ggrid(BATCH / 128, 1, AGENTS);
    size_t smem144 = 4 * (size_t)128 * (144 + 8) * 2;   // 155648
    size_t smem128 = 4 * (size_t)128 * (128 + 8) * 2;   // 139264

    // sa = lrelu(bn([obs|actions]) @ W_sa + b_sa)   K=144
    gemm_mma<<<ggrid, 256, smem144>>>(obs, (long)BATCH * OBS, OBS,
                                      actions, (long)BATCH * ACT, ACT, OBS,
                                      i_sa_h, i_sa_l, (long)HID * INP, INP, INP,
                                      bsaf, HID, sa, sRow, 1);
    // se = lrelu(bn(obs) @ W_s + b_s)   K=128
    gemm_mma<<<ggrid, 256, smem128>>>(obs, (long)BATCH * OBS, OBS,
                                      nullptr, 0, 0, 1 << 30,
                                      i_s_h, i_s_l, (long)HID * OBS, OBS, OBS,
                                      bsf, HID, se, sRow, 1);
    // keys = sa @ Wk
    gemm_mma<<<ggrid, 256, smem128>>>(sa, sRow, HID, nullptr, 0, 0, 1 << 30,
                                      i_k_h, i_k_l, 0, HID, HID,
                                      nullptr, 0, Kt, sRow, 0);
    // vals = lrelu(sa @ Wv + bv)
    gemm_mma<<<ggrid, 256, smem128>>>(sa, sRow, HID, nullptr, 0, 0, 1 << 30,
                                      i_v_h, i_v_l, 0, HID, HID,
                                      bv, 0, Vt, sRow, 1);
    // sel = se @ Wsel
    gemm_mma<<<ggrid, 256, smem128>>>(se, sRow, HID, nullptr, 0, 0, 1 << 30,
                                      i_sel_h, i_sel_l, 0, HID, HID,
                                      nullptr, 0, St, sRow, 0);

    attn_kernel<<<(BATCH * 64) / 8, 256>>>(Kt, St, Vt, other);

    // h = lrelu([se | other] @ Wc1 + bc1)   K=256 -> 2 chunks of 128
    gemm_mma<<<ggrid, 256, smem128>>>(se, sRow, HID,
                                      other, sRow, HID, HID,
                                      i_c1_h, i_c1_l, (long)HID * 2 * HID, 2 * HID, HID,
                                      bc1, HID, hbuf, sRow, 1);

    final_kernel<<<(AGENTS * BATCH) / 8, 256>>>(hbuf, actions, Wc2, bc2, out);
}

// round 5
// speedup vs baseline: 2.2543x; 1.3123x over previous
#include <cuda_runtime.h>
#include <cuda_bf16.h>
#include <cstdint>

#define AGENTS 16
#define BATCH  8192
#define OBS    128
#define ACT    16
#define HID    128
#define NHEAD  4
#define DHEAD  32
#define INP    (OBS + ACT)   // 144

// ---------------- scratch (static device globals; no runtime alloc) -----------
__device__ float g_ps [AGENTS * 160 * 8];
__device__ float g_ps2[AGENTS * 160 * 8];
__device__ float g_mean[AGENTS * INP];
__device__ float g_istd[AGENTS * INP];
__device__ float g_Wsaf[AGENTS * INP * HID];
__device__ float g_Wsf [AGENTS * OBS * HID];
__device__ float g_b1  [AGENTS * 256];       // [bsaf | bsf]
__device__ float g_bkv [256];                // [0 | bv]
// bf16 hi/lo weight images, [n][k] row-major (B^T)
__device__ __nv_bfloat16 w1_hi [(long)AGENTS * 256 * INP];
__device__ __nv_bfloat16 w1_lo [(long)AGENTS * 256 * INP];
__device__ __nv_bfloat16 wkv_hi[256 * HID];
__device__ __nv_bfloat16 wkv_lo[256 * HID];
__device__ __nv_bfloat16 wsel_hi[HID * HID];
__device__ __nv_bfloat16 wsel_lo[HID * HID];
__device__ __nv_bfloat16 wc1_hi[(long)AGENTS * HID * 2 * HID];
__device__ __nv_bfloat16 wc1_lo[(long)AGENTS * HID * 2 * HID];
// fp32 activations
__device__ float g_ase  [(long)AGENTS * BATCH * 256];   // [sa | se]
__device__ float g_KV   [(long)AGENTS * BATCH * 256];   // [K | V]
__device__ float g_S    [(long)AGENTS * BATCH * HID];
__device__ float g_other[(long)AGENTS * BATCH * HID];

// ---------------- helpers ------------------------------------------------------
__device__ __forceinline__ uint32_t smem_u32(const void* p) {
    uint32_t r;
    asm("{ .reg .u64 t; cvta.to.shared.u64 t, %1; cvt.u32.u64 %0, t; }" : "=r"(r) : "l"(p));
    return r;
}
__device__ __forceinline__ void ldm_x4(uint32_t* r, uint32_t addr) {
    asm volatile("ldmatrix.sync.aligned.m8n8.x4.shared.b16 {%0,%1,%2,%3}, [%4];"
                 : "=r"(r[0]), "=r"(r[1]), "=r"(r[2]), "=r"(r[3]) : "r"(addr));
}
__device__ __forceinline__ void mma_bf16(float* c, const uint32_t* a, uint32_t b0, uint32_t b1) {
    asm volatile("mma.sync.aligned.m16n8k16.row.col.f32.bf16.bf16.f32 "
                 "{%0,%1,%2,%3}, {%4,%5,%6,%7}, {%8,%9}, {%0,%1,%2,%3};"
                 : "+f"(c[0]), "+f"(c[1]), "+f"(c[2]), "+f"(c[3])
                 : "r"(a[0]), "r"(a[1]), "r"(a[2]), "r"(a[3]), "r"(b0), "r"(b1));
}

// ---------------- BN pass 1: partial sums over batch segments ------------------
__global__ void bn_part_kernel(const float* __restrict__ obs,
                               const float* __restrict__ actions,
                               float* __restrict__ ps, float* __restrict__ ps2)
{
    int a = blockIdx.x;
    int f = blockIdx.y * 32 + threadIdx.x;
    int seg = blockIdx.z;
    float s = 0.f, s2 = 0.f;
    if (f < INP) {
        if (f < OBS) {
            const float* src = obs + (long)a * BATCH * OBS + (long)seg * 1024 * OBS + f;
            for (int b = threadIdx.y; b < 1024; b += 32) {
                float x = src[(long)b * OBS]; s += x; s2 += x * x;
            }
        } else {
            const float* src = actions + (long)a * BATCH * ACT + (long)seg * 1024 * ACT + (f - OBS);
            for (int b = threadIdx.y; b < 1024; b += 32) {
                float x = src[(long)b * ACT]; s += x; s2 += x * x;
            }
        }
    }
    __shared__ float sh1[32][33];
    __shared__ float sh2[32][33];
    sh1[threadIdx.y][threadIdx.x] = s;
    sh2[threadIdx.y][threadIdx.x] = s2;
    __syncthreads();
    for (int st = 16; st > 0; st >>= 1) {
        if (threadIdx.y < st) {
            sh1[threadIdx.y][threadIdx.x] += sh1[threadIdx.y + st][threadIdx.x];
            sh2[threadIdx.y][threadIdx.x] += sh2[threadIdx.y + st][threadIdx.x];
        }
        __syncthreads();
    }
    if (threadIdx.y == 0) {
        int fi = blockIdx.y * 32 + threadIdx.x;
        ps [(a * 160 + fi) * 8 + seg] = sh1[0][threadIdx.x];
        ps2[(a * 160 + fi) * 8 + seg] = sh2[0][threadIdx.x];
    }
}

// ---------------- BN pass 2: finalize mean / istd -------------------------------
__global__ void bn_fin_kernel(const float* __restrict__ ps, const float* __restrict__ ps2,
                              float* __restrict__ mean, float* __restrict__ istd)
{
    int a = blockIdx.x;
    int f = threadIdx.x;       // 0..159
    if (f >= INP) return;
    float s = 0.f, s2 = 0.f;
    for (int seg = 0; seg < 8; seg++) {
        s  += ps [(a * 160 + f) * 8 + seg];
        s2 += ps2[(a * 160 + f) * 8 + seg];
    }
    float m = s * (1.0f / BATCH);
    float v = s2 * (1.0f / BATCH) - m * m;
    mean[a * INP + f] = m;
    istd[a * INP + f] = rsqrtf(v + 1e-5f);
}

// ---------------- fold BN into first-layer weights + combined bias -------------
__global__ void fold_kernel(const float* __restrict__ W_sa, const float* __restrict__ b_sa,
                            const float* __restrict__ W_s,  const float* __restrict__ b_s,
                            const float* __restrict__ mean, const float* __restrict__ istd,
                            float* __restrict__ Wsaf, float* __restrict__ Wsf,
                            float* __restrict__ b1)
{
    int a = blockIdx.x;
    int h = threadIdx.x;
    if (blockIdx.y == 0) {
        float acc = 0.f;
        for (int k = 0; k < INP; k++) {
            float w  = W_sa[((long)a * INP + k) * HID + h];
            float is = istd[a * INP + k];
            float m  = mean[a * INP + k];
            Wsaf[((long)a * INP + k) * HID + h] = w * is;
            acc += m * is * w;
        }
        b1[a * 256 + h] = b_sa[a * HID + h] - acc;
    } else {
        float acc = 0.f;
        for (int k = 0; k < OBS; k++) {
            float w  = W_s[((long)a * OBS + k) * HID + h];
            float is = istd[a * INP + k];
            float m  = mean[a * INP + k];
            Wsf[((long)a * OBS + k) * HID + h] = w * is;
            acc += m * is * w;
        }
        b1[a * 256 + 128 + h] = b_s[a * HID + h] - acc;
    }
}

// ---------------- build all bf16 hi/lo weight images ---------------------------
// y=0: W1 [256][144] per agent; y=1: KV [256][128] shared; y=2: Sel [128][128];
// y=3: C1 [128][256] per agent.
__global__ void prep_kernel(const float* __restrict__ Wsaf, const float* __restrict__ Wsf,
                            const float* __restrict__ Wk, const float* __restrict__ Wsel,
                            const float* __restrict__ Wv, const float* __restrict__ bv,
                            const float* __restrict__ Wc1,
                            __nv_bfloat16* __restrict__ w1h, __nv_bfloat16* __restrict__ w1l,
                            __nv_bfloat16* __restrict__ kvh, __nv_bfloat16* __restrict__ kvl,
                            __nv_bfloat16* __restrict__ selh, __nv_bfloat16* __restrict__ sell,
                            __nv_bfloat16* __restrict__ c1h, __nv_bfloat16* __restrict__ c1l,
                            float* __restrict__ bkv)
{
    int img = blockIdx.y;
    int a = blockIdx.z;
    int e = blockIdx.x * 256 + threadIdx.x;
    float v;
    __nv_bfloat16* hp;
    __nv_bfloat16* lp;
    long dst;

    if (img == 0) {
        if (e >= 256 * INP) return;
        int n = e / INP, k = e - n * INP;
        if (n < 128) v = Wsaf[((long)a * INP + k) * HID + n];
        else         v = (k < OBS) ? Wsf[((long)a * OBS + k) * HID + (n - 128)] : 0.f;
        hp = w1h; lp = w1l; dst = (long)a * 256 * INP + e;
    } else if (img == 1) {
        if (a != 0) return;
        if (e < 256 && blockIdx.x == (256 * HID) / 256) { /* unreachable pad */ }
        if (e >= 256 * HID) return;
        int n = e / HID, k = e - n * HID;
        if (n < 128) v = Wk[(((n >> 5) * HID) + k) * DHEAD + (n & 31)];
        else {
            int n2 = n - 128;
            v = Wv[(((n2 >> 5) * HID) + k) * DHEAD + (n2 & 31)];
        }
        if (e < 256) bkv[e] = (e < 128) ? 0.f : bv[e - 128];
        hp = kvh; lp = kvl; dst = e;
    } else if (img == 2) {
        if (a != 0) return;
        if (e >= HID * HID) return;
        int n = e / HID, k = e - n * HID;
        v = Wsel[(((n >> 5) * HID) + k) * DHEAD + (n & 31)];
        hp = selh; lp = sell; dst = e;
    } else {
        if (e >= HID * 2 * HID) return;
        int n = e / (2 * HID), k = e - n * (2 * HID);
        v = Wc1[((long)a * 2 * HID + k) * HID + n];
        hp = c1h; lp = c1l; dst = (long)a * HID * 2 * HID + e;
    }
    __nv_bfloat16 h = __float2bfloat16(v);
    __nv_bfloat16 l = __float2bfloat16(v - __bfloat162float(h));
    hp[dst] = h;
    lp[dst] = l;
}

// ---------------- tensor-core GEMM via mma.sync (bf16x3 split, fp32 accum) ----
// C[m, colBase+n] = act( sum_k A[m,k] * Bt[colBase+n, k] + bias[colBase+n] )
// act applied when global col >= actFrom. Optional fused final epilogue.
__global__ void __launch_bounds__(256, 2) gemm_mma(
    const float* __restrict__ A0, long sA0, int lda0,
    const float* __restrict__ A1, long sA1, int lda1, int ksplit,
    const __nv_bfloat16* __restrict__ Bhi, const __nv_bfloat16* __restrict__ Blo, long sB,
    int Ktot, int chunkK,
    const float* __restrict__ bias, long sBias,
    float* __restrict__ C, long sC, int ldc, int actFrom,
    int fuseFinal,
    const float* __restrict__ actions, const float* __restrict__ Wc2,
    const float* __restrict__ bc2, float* __restrict__ outq)
{
    extern __shared__ __nv_bfloat16 sm[];
    __shared__ float sWc2[HID * ACT];
    __shared__ int   sIdx[128];
    __shared__ float sQred[2][128];

    const int stride = chunkK + 8;
    __nv_bfloat16* Ah = sm;
    __nv_bfloat16* Al = Ah + 128 * stride;
    __nv_bfloat16* Bh = Al + 128 * stride;
    __nv_bfloat16* Bl = Bh + 128 * stride;

    int tid = threadIdx.x, wid = tid >> 5, lane = tid & 31;
    int a = blockIdx.z;
    int colBase = blockIdx.y * 128;
    long mBase = (long)blockIdx.x * 128;
    int wm = (wid & 3) * 32;
    int wn = (wid >> 2) * 64;

    const float* A0p = A0 + (long)a * sA0;
    const float* A1p = A1 ? A1 + (long)a * sA1 : nullptr;
    const __nv_bfloat16* BhP = Bhi + (long)a * sB + (long)colBase * Ktot;
    const __nv_bfloat16* BlP = Blo + (long)a * sB + (long)colBase * Ktot;

    // fused-final prologue: argmax idx per row + Wc2 in smem (before first sync)
    if (fuseFinal) {
        for (int i = tid; i < HID * ACT; i += 256)
            sWc2[i] = Wc2[(long)a * HID * ACT + i];
        if (tid < 128) {
            const float* ap = actions + ((long)a * BATCH + mBase + tid) * ACT;
            float best = ap[0]; int bi = 0;
#pragma unroll
            for (int j = 1; j < ACT; j++) {
                float x = ap[j];
                if (x > best) { best = x; bi = j; }
            }
            sIdx[tid] = bi;
        }
    }

    float acc[2][8][4];
#pragma unroll
    for (int i = 0; i < 2; i++)
#pragma unroll
        for (int j = 0; j < 8; j++)
#pragma unroll
            for (int q = 0; q < 4; q++) acc[i][j][q] = 0.f;

    int nChunks = Ktot / chunkK;
    int kq4 = chunkK >> 2;

    for (int c = 0; c < nChunks; c++) {
        if (c > 0) __syncthreads();
        int k0 = c * chunkK;

        // ---- load A chunk fp32 -> split hi/lo bf16 ----
        for (int i = tid; i < 128 * kq4; i += 256) {
            int row = i / kq4;
            int kq = (i - row * kq4) * 4;
            int kg = k0 + kq;
            const float* p;
            if (kg < ksplit) p = A0p + (mBase + row) * (long)lda0 + kg;
            else             p = A1p + (mBase + row) * (long)lda1 + (kg - ksplit);
            float4 v = *(const float4*)p;
            __nv_bfloat16 h0 = __float2bfloat16(v.x), h1 = __float2bfloat16(v.y);
            __nv_bfloat16 h2 = __float2bfloat16(v.z), h3 = __float2bfloat16(v.w);
            __nv_bfloat16 l0 = __float2bfloat16(v.x - __bfloat162float(h0));
            __nv_bfloat16 l1 = __float2bfloat16(v.y - __bfloat162float(h1));
            __nv_bfloat16 l2 = __float2bfloat16(v.z - __bfloat162float(h2));
            __nv_bfloat16 l3 = __float2bfloat16(v.w - __bfloat162float(h3));
            int off = row * stride + kq;
            uint2 ph, pl;
            ph.x = (uint32_t)__bfloat16_as_ushort(h0) | ((uint32_t)__bfloat16_as_ushort(h1) << 16);
            ph.y = (uint32_t)__bfloat16_as_ushort(h2) | ((uint32_t)__bfloat16_as_ushort(h3) << 16);
            pl.x = (uint32_t)__bfloat16_as_ushort(l0) | ((uint32_t)__bfloat16_as_ushort(l1) << 16);
            pl.y = (uint32_t)__bfloat16_as_ushort(l2) | ((uint32_t)__bfloat16_as_ushort(l3) << 16);
            *(uint2*)(Ah + off) = ph;
            *(uint2*)(Al + off) = pl;
        }
        // ---- copy B chunk (bf16 images) ----
        int kq8 = chunkK >> 3;
        for (int i = tid; i < 128 * kq8; i += 256) {
            int n = i / kq8;
            int kk = (i - n * kq8) * 8;
            const uint4* sh = (const uint4*)(BhP + (long)n * Ktot + k0 + kk);
            const uint4* sl = (const uint4*)(BlP + (long)n * Ktot + k0 + kk);
            int off = n * stride + kk;
            *(uint4*)(Bh + off) = *sh;
            *(uint4*)(Bl + off) = *sl;
        }
        __syncthreads();

        // ---- compute ----
        uint32_t aBase = smem_u32(Ah);
        uint32_t alBase = smem_u32(Al);
        uint32_t bBase = smem_u32(Bh);
        uint32_t blBase = smem_u32(Bl);
        int lr16 = lane & 15, lh16 = (lane >> 4) * 8;
        int lr8 = lane & 7, lk8 = ((lane >> 3) & 1) * 8, ln8 = (lane >> 4) * 8;

        for (int ks = 0; ks < chunkK; ks += 16) {
            uint32_t ah[2][4], al[2][4];
#pragma unroll
            for (int mi = 0; mi < 2; mi++) {
                uint32_t addr = aBase + (uint32_t)(((wm + mi * 16 + lr16) * stride + ks + lh16) * 2);
                ldm_x4(ah[mi], addr);
                addr = alBase + (uint32_t)(((wm + mi * 16 + lr16) * stride + ks + lh16) * 2);
                ldm_x4(al[mi], addr);
            }
#pragma unroll
            for (int ni4 = 0; ni4 < 4; ni4++) {
                int n0 = wn + ni4 * 16;
                uint32_t boff = (uint32_t)(((n0 + ln8 + lr8) * stride + ks + lk8) * 2);
                uint32_t bh[4], bl[4];
                ldm_x4(bh, bBase + boff);
                ldm_x4(bl, blBase + boff);
#pragma unroll
                for (int mi = 0; mi < 2; mi++) {
                    mma_bf16(acc[mi][ni4 * 2],     ah[mi], bh[0], bh[1]);
                    mma_bf16(acc[mi][ni4 * 2 + 1], ah[mi], bh[2], bh[3]);
                    mma_bf16(acc[mi][ni4 * 2],     ah[mi], bl[0], bl[1]);
                    mma_bf16(acc[mi][ni4 * 2 + 1], ah[mi], bl[2], bl[3]);
                    mma_bf16(acc[mi][ni4 * 2],     al[mi], bh[0], bh[1]);
                    mma_bf16(acc[mi][ni4 * 2 + 1], al[mi], bh[2], bh[3]);
                }
            }
        }
    }

    // ---- epilogue ----
    int gr = lane >> 2, tg = lane & 3;

    if (!fuseFinal) {
        float* Cp = C + (long)a * sC;
#pragma unroll
        for (int mi = 0; mi < 2; mi++) {
            long row0 = mBase + wm + mi * 16 + gr;
            long row1 = row0 + 8;
#pragma unroll
            for (int ni = 0; ni < 8; ni++) {
                int col = colBase + wn + ni * 8 + tg * 2;
                float b0 = 0.f, b1 = 0.f;
                if (bias) {
                    const float* bp = bias + (long)a * sBias + col;
                    b0 = bp[0]; b1 = bp[1];
                }
                float v0 = acc[mi][ni][0] + b0;
                float v1 = acc[mi][ni][1] + b1;
                float v2 = acc[mi][ni][2] + b0;
                float v3 = acc[mi][ni][3] + b1;
                if (col >= actFrom) {
                    v0 = v0 > 0.f ? v0 : 0.01f * v0;
                    v2 = v2 > 0.f ? v2 : 0.01f * v2;
                }
                if (col + 1 >= actFrom) {
                    v1 = v1 > 0.f ? v1 : 0.01f * v1;
                    v3 = v3 > 0.f ? v3 : 0.01f * v3;
                }
                *(float2*)(Cp + row0 * ldc + col) = make_float2(v0, v1);
                *(float2*)(Cp + row1 * ldc + col) = make_float2(v2, v3);
            }
        }
    } else {
        // fused final: h = lrelu(acc + bias); q = h . Wc2[:, idx] + bc2[idx]
        float p[4] = {0.f, 0.f, 0.f, 0.f};   // per thread: rows r0, r0+8, r0+16.., per mi
        int rl0 = wm + gr;                   // mi=0 row local
#pragma unroll
        for (int mi = 0; mi < 2; mi++) {
            int ra = wm + mi * 16 + gr;
            int rb = ra + 8;
            int ia = sIdx[ra], ib = sIdx[rb];
#pragma unroll
            for (int ni = 0; ni < 8; ni++) {
                int col = wn + ni * 8 + tg * 2;
                const float* bp = bias + (long)a * sBias + col;
                float b0 = bp[0], b1 = bp[1];
                float v0 = acc[mi][ni][0] + b0;
                float v1 = acc[mi][ni][1] + b1;
                float v2 = acc[mi][ni][2] + b0;
                float v3 = acc[mi][ni][3] + b1;
                v0 = v0 > 0.f ? v0 : 0.01f * v0;
                v1 = v1 > 0.f ? v1 : 0.01f * v1;
                v2 = v2 > 0.f ? v2 : 0.01f * v2;
                v3 = v3 > 0.f ? v3 : 0.01f * v3;
                p[mi * 2]     += v0 * sWc2[col * ACT + ia] + v1 * sWc2[(col + 1) * ACT + ia];
                p[mi * 2 + 1] += v2 * sWc2[col * ACT + ib] + v3 * sWc2[(col + 1) * ACT + ib];
            }
        }
        // reduce over tg (4 lanes)
#pragma unroll
        for (int q = 0; q < 4; q++) {
            p[q] += __shfl_xor_sync(0xffffffffu, p[q], 1);
            p[q] += __shfl_xor_sync(0xffffffffu, p[q], 2);
        }
        int nh = wid >> 2;
        if (tg == 0) {
            sQred[nh][wm + gr]      = p[0];
            sQred[nh][wm + gr + 8]  = p[1];
            sQred[nh][wm + gr + 16] = p[2];
            sQred[nh][wm + gr + 24] = p[3];
        }
        __syncthreads();
        if (tid < 128) {
            float q = sQred[0][tid] + sQred[1][tid] + bc2[a * ACT + sIdx[tid]];
            outq[(long)a * BATCH + mBase + tid] = q;
        }
        (void)rl0;
    }
}

// ---------------- attention: one warp per (head, agent_i, batch) --------------
__global__ void attn_kernel(const float* __restrict__ KV, const float* __restrict__ St,
                            float* __restrict__ other)
{
    int gw   = blockIdx.x * 8 + (threadIdx.x >> 5);
    int lane = threadIdx.x & 31;
    int b = gw >> 6;
    int r = gw & 63;
    int n = r >> 4;
    int i = r & 15;
    int col = n * DHEAD + lane;

    float selv = St[((long)i * BATCH + b) * HID + col];
    float lg = -3e38f;
#pragma unroll
    for (int j = 0; j < 16; j++) {
        float p = selv * KV[((long)j * BATCH + b) * 256 + col];
#pragma unroll
        for (int off = 16; off; off >>= 1) p += __shfl_xor_sync(0xffffffffu, p, off);
        if (lane == j) lg = (j == i) ? -1e9f : p * 0.17677669529663687f;
    }
    float mx = lg;
#pragma unroll
    for (int off = 16; off; off >>= 1) mx = fmaxf(mx, __shfl_xor_sync(0xffffffffu, mx, off));
    float e = (lane < 16) ? __expf(lg - mx) : 0.f;
    float den = e;
#pragma unroll
    for (int off = 16; off; off >>= 1) den += __shfl_xor_sync(0xffffffffu, den, off);
    float w = e / den;

    float acc = 0.f;
#pragma unroll
    for (int j = 0; j < 16; j++) {
        float wj = __shfl_sync(0xffffffffu, w, j);
        acc = fmaf(wj, KV[((long)j * BATCH + b) * 256 + 128 + col], acc);
    }
    other[((long)i * BATCH + b) * HID + col] = acc;
}

// ---------------- launch -------------------------------------------------------
static float* symaddr(const void* sym)
{
    void* p = nullptr;
    cudaGetSymbolAddress(&p, sym);
    return (float*)p;
}
static __nv_bfloat16* symaddr_bf(const void* sym)
{
    void* p = nullptr;
    cudaGetSymbolAddress(&p, sym);
    return (__nv_bfloat16*)p;
}

extern "C" void kernel_launch(void* const* d_in, const int* in_sizes, int n_in,
                              void* d_out, int out_size)
{
    const float* obs     = (const float*)d_in[0];
    const float* actions = (const float*)d_in[1];
    const float* W_sa    = (const float*)d_in[2];
    const float* b_sa    = (const float*)d_in[3];
    const float* W_s     = (const float*)d_in[4];
    const float* b_s     = (const float*)d_in[5];
    const float* Wk      = (const float*)d_in[6];
    const float* Wsel    = (const float*)d_in[7];
    const float* Wv      = (const float*)d_in[8];
    const float* bv      = (const float*)d_in[9];
    const float* Wc1     = (const float*)d_in[10];
    const float* bc1     = (const float*)d_in[11];
    const float* Wc2     = (const float*)d_in[12];
    const float* bc2     = (const float*)d_in[13];
    float* out = (float*)d_out;

    float* ps    = symaddr(g_ps);
    float* ps2   = symaddr(g_ps2);
    float* mean  = symaddr(g_mean);
    float* istd  = symaddr(g_istd);
    float* Wsaf  = symaddr(g_Wsaf);
    float* Wsf   = symaddr(g_Wsf);
    float* b1    = symaddr(g_b1);
    float* bkv   = symaddr(g_bkv);
    float* ase   = symaddr(g_ase);
    float* KV    = symaddr(g_KV);
    float* St    = symaddr(g_S);
    float* other = symaddr(g_other);

    __nv_bfloat16* w1h  = symaddr_bf(w1_hi);
    __nv_bfloat16* w1l  = symaddr_bf(w1_lo);
    __nv_bfloat16* kvh  = symaddr_bf(wkv_hi);
    __nv_bfloat16* kvl  = symaddr_bf(wkv_lo);
    __nv_bfloat16* selh = symaddr_bf(wsel_hi);
    __nv_bfloat16* sell = symaddr_bf(wsel_lo);
    __nv_bfloat16* c1h  = symaddr_bf(wc1_hi);
    __nv_bfloat16* c1l  = symaddr_bf(wc1_lo);

    static bool attr_set = false;
    if (!attr_set) {
        cudaFuncSetAttribute(gemm_mma, cudaFuncAttributeMaxDynamicSharedMemorySize, 100000);
        attr_set = true;
    }

    // 0: BN partials, 1: BN finalize, 2: fold, 3: prep images
    bn_part_kernel<<<dim3(AGENTS, 5, 8), dim3(32, 32)>>>(obs, actions, ps, ps2);
    bn_fin_kernel<<<AGENTS, 160>>>(ps, ps2, mean, istd);
    fold_kernel<<<dim3(AGENTS, 2), HID>>>(W_sa, b_sa, W_s, b_s, mean, istd, Wsaf, Wsf, b1);
    prep_kernel<<<dim3(144, 4, AGENTS), 256>>>(Wsaf, Wsf, Wk, Wsel, Wv, bv, Wc1,
                                               w1h, w1l, kvh, kvl, selh, sell, c1h, c1l, bkv);

    const long sASE = (long)BATCH * 256;
    const long sH   = (long)BATCH * HID;

    // 4: ase = lrelu(bn([obs|act]) @ [W_sa|W_s] + b1)  K=144, N=256, chunk 48
    size_t smem48 = 4 * (size_t)128 * (48 + 8) * 2;
    gemm_mma<<<dim3(BATCH / 128, 2, AGENTS), 256, smem48>>>(
        obs, (long)BATCH * OBS, OBS, actions, (long)BATCH * ACT, ACT, OBS,
        w1h, w1l, (long)256 * INP, INP, 48,
        b1, 256, ase, sASE, 256, 0,
        0, nullptr, nullptr, nullptr, nullptr);

    // 5 (profiled): KV = sa @ [Wk|Wv] (+bv, act on V half)  K=128, N=256, chunk 64
    size_t smem64 = 4 * (size_t)128 * (64 + 8) * 2;
    gemm_mma<<<dim3(BATCH / 128, 2, AGENTS), 256, smem64>>>(
        ase, sASE, 256, nullptr, 0, 0, 1 << 30,
        kvh, kvl, 0, HID, 64,
        bkv, 0, KV, sASE, 256, 128,
        0, nullptr, nullptr, nullptr, nullptr);

    // 6: S = se @ Wsel  K=128, N=128
    gemm_mma<<<dim3(BATCH / 128, 1, AGENTS), 256, smem64>>>(
        ase + 128, sASE, 256, nullptr, 0, 0, 1 << 30,
        selh, sell, 0, HID, 64,
        nullptr, 0, St, sH, 128, 1 << 30,
        0, nullptr, nullptr, nullptr, nullptr);

    // 7: attention
    attn_kernel<<<(BATCH * 64) / 8, 256>>>(KV, St, other);

    // 8: q = fused( lrelu([se|other] @ Wc1 + bc1) . Wc2[:,argmax] + bc2 )  K=256
    gemm_mma<<<dim3(BATCH / 128, 1, AGENTS), 256, smem64>>>(
        ase + 128, sASE, 256, other, sH, HID, HID,
        c1h, c1l, (long)HID * 2 * HID, 2 * HID, 64,
        bc1, HID, nullptr, 0, 0, 0,
        1, actions, Wc2, bc2, out);
}

// round 6
// speedup vs baseline: 2.8249x; 1.2531x over previous
#include <cuda_runtime.h>
#include <cuda_bf16.h>
#include <cstdint>

#define AGENTS 16
#define BATCH  8192
#define OBS    128
#define ACT    16
#define HID    128
#define NHEAD  4
#define DHEAD  32
#define INP    (OBS + ACT)   // 144

// ---------------- scratch (static device globals; no runtime alloc) -----------
__device__ float g_ps [AGENTS * 160 * 8];
__device__ float g_ps2[AGENTS * 160 * 8];
__device__ float g_mean[AGENTS * INP];
__device__ float g_istd[AGENTS * INP];
__device__ float g_Wsaf[AGENTS * INP * HID];
__device__ float g_Wsf [AGENTS * OBS * HID];
__device__ float g_b1  [AGENTS * 256];       // [bsaf | bsf]
__device__ float g_bkv [256];                // [0 | bv]
// bf16 hi/lo weight images, [n][k] row-major (B^T)
__device__ __nv_bfloat16 w1_hi [(long)AGENTS * 256 * INP];
__device__ __nv_bfloat16 w1_lo [(long)AGENTS * 256 * INP];
__device__ __nv_bfloat16 wkv_hi[256 * HID];
__device__ __nv_bfloat16 wkv_lo[256 * HID];
__device__ __nv_bfloat16 wsel_hi[HID * HID];
__device__ __nv_bfloat16 wsel_lo[HID * HID];
__device__ __nv_bfloat16 wc1_hi[(long)AGENTS * HID * 2 * HID];
__device__ __nv_bfloat16 wc1_lo[(long)AGENTS * HID * 2 * HID];
// bf16 hi/lo activation planes
__device__ __nv_bfloat16 g_obsH[(long)AGENTS * BATCH * OBS];
__device__ __nv_bfloat16 g_obsL[(long)AGENTS * BATCH * OBS];
__device__ __nv_bfloat16 g_actH[(long)AGENTS * BATCH * ACT];
__device__ __nv_bfloat16 g_actL[(long)AGENTS * BATCH * ACT];
__device__ __nv_bfloat16 g_aseH[(long)AGENTS * BATCH * 256];   // [sa | se]
__device__ __nv_bfloat16 g_aseL[(long)AGENTS * BATCH * 256];
__device__ __nv_bfloat16 g_othH[(long)AGENTS * BATCH * HID];
__device__ __nv_bfloat16 g_othL[(long)AGENTS * BATCH * HID];
// fp32 buffers for attention inputs
__device__ float g_KV   [(long)AGENTS * BATCH * 256];   // [K | V]
__device__ float g_S    [(long)AGENTS * BATCH * HID];

// ---------------- helpers ------------------------------------------------------
__device__ __forceinline__ uint32_t smem_u32(const void* p) {
    uint32_t r;
    asm("{ .reg .u64 t; cvta.to.shared.u64 t, %1; cvt.u32.u64 %0, t; }" : "=r"(r) : "l"(p));
    return r;
}
__device__ __forceinline__ void ldm_x4(uint32_t* r, uint32_t addr) {
    asm volatile("ldmatrix.sync.aligned.m8n8.x4.shared.b16 {%0,%1,%2,%3}, [%4];"
                 : "=r"(r[0]), "=r"(r[1]), "=r"(r[2]), "=r"(r[3]) : "r"(addr));
}
__device__ __forceinline__ void mma_bf16(float* c, const uint32_t* a, uint32_t b0, uint32_t b1) {
    asm volatile("mma.sync.aligned.m16n8k16.row.col.f32.bf16.bf16.f32 "
                 "{%0,%1,%2,%3}, {%4,%5,%6,%7}, {%8,%9}, {%0,%1,%2,%3};"
                 : "+f"(c[0]), "+f"(c[1]), "+f"(c[2]), "+f"(c[3])
                 : "r"(a[0]), "r"(a[1]), "r"(a[2]), "r"(a[3]), "r"(b0), "r"(b1));
}
__device__ __forceinline__ void cp16(uint32_t dst, const void* src) {
    asm volatile("cp.async.cg.shared.global [%0], [%1], 16;" :: "r"(dst), "l"(src));
}
__device__ __forceinline__ void cp_wait() {
    asm volatile("cp.async.commit_group;\ncp.async.wait_group 0;" ::: "memory");
}
__device__ __forceinline__ uint32_t pack_bf16(float x, float y) {
    __nv_bfloat16 hx = __float2bfloat16(x), hy = __float2bfloat16(y);
    return (uint32_t)__bfloat16_as_ushort(hx) | ((uint32_t)__bfloat16_as_ushort(hy) << 16);
}

// ---------------- BN pass 1: partial sums + split planes ----------------------
__global__ void bn_part_kernel(const float* __restrict__ obs,
                               const float* __restrict__ actions,
                               float* __restrict__ ps, float* __restrict__ ps2,
                               __nv_bfloat16* __restrict__ oH, __nv_bfloat16* __restrict__ oL,
                               __nv_bfloat16* __restrict__ aH, __nv_bfloat16* __restrict__ aL)
{
    int a = blockIdx.x;
    int f = blockIdx.y * 32 + threadIdx.x;
    int seg = blockIdx.z;
    float s = 0.f, s2 = 0.f;
    if (f < INP) {
        if (f < OBS) {
            const float* src = obs + (long)a * BATCH * OBS + (long)seg * 1024 * OBS + f;
            __nv_bfloat16* dH = oH + (long)a * BATCH * OBS + (long)seg * 1024 * OBS + f;
            __nv_bfloat16* dL = oL + (long)a * BATCH * OBS + (long)seg * 1024 * OBS + f;
            for (int b = threadIdx.y; b < 1024; b += 32) {
                float x = src[(long)b * OBS]; s += x; s2 += x * x;
                __nv_bfloat16 h = __float2bfloat16(x);
                dH[(long)b * OBS] = h;
                dL[(long)b * OBS] = __float2bfloat16(x - __bfloat162float(h));
            }
        } else {
            const float* src = actions + (long)a * BATCH * ACT + (long)seg * 1024 * ACT + (f - OBS);
            __nv_bfloat16* dH = aH + (long)a * BATCH * ACT + (long)seg * 1024 * ACT + (f - OBS);
            __nv_bfloat16* dL = aL + (long)a * BATCH * ACT + (long)seg * 1024 * ACT + (f - OBS);
            for (int b = threadIdx.y; b < 1024; b += 32) {
                float x = src[(long)b * ACT]; s += x; s2 += x * x;
                __nv_bfloat16 h = __float2bfloat16(x);
                dH[(long)b * ACT] = h;
                dL[(long)b * ACT] = __float2bfloat16(x - __bfloat162float(h));
            }
        }
    }
    __shared__ float sh1[32][33];
    __shared__ float sh2[32][33];
    sh1[threadIdx.y][threadIdx.x] = s;
    sh2[threadIdx.y][threadIdx.x] = s2;
    __syncthreads();
    for (int st = 16; st > 0; st >>= 1) {
        if (threadIdx.y < st) {
            sh1[threadIdx.y][threadIdx.x] += sh1[threadIdx.y + st][threadIdx.x];
            sh2[threadIdx.y][threadIdx.x] += sh2[threadIdx.y + st][threadIdx.x];
        }
        __syncthreads();
    }
    if (threadIdx.y == 0) {
        int fi = blockIdx.y * 32 + threadIdx.x;
        ps [(a * 160 + fi) * 8 + seg] = sh1[0][threadIdx.x];
        ps2[(a * 160 + fi) * 8 + seg] = sh2[0][threadIdx.x];
    }
}

// ---------------- BN pass 2: finalize mean / istd -------------------------------
__global__ void bn_fin_kernel(const float* __restrict__ ps, const float* __restrict__ ps2,
                              float* __restrict__ mean, float* __restrict__ istd)
{
    int a = blockIdx.x;
    int f = threadIdx.x;
    if (f >= INP) return;
    float s = 0.f, s2 = 0.f;
    for (int seg = 0; seg < 8; seg++) {
        s  += ps [(a * 160 + f) * 8 + seg];
        s2 += ps2[(a * 160 + f) * 8 + seg];
    }
    float m = s * (1.0f / BATCH);
    float v = s2 * (1.0f / BATCH) - m * m;
    mean[a * INP + f] = m;
    istd[a * INP + f] = rsqrtf(v + 1e-5f);
}

// ---------------- fold BN into first-layer weights + combined bias -------------
__global__ void fold_kernel(const float* __restrict__ W_sa, const float* __restrict__ b_sa,
                            const float* __restrict__ W_s,  const float* __restrict__ b_s,
                            const float* __restrict__ mean, const float* __restrict__ istd,
                            float* __restrict__ Wsaf, float* __restrict__ Wsf,
                            float* __restrict__ b1)
{
    int a = blockIdx.x;
    int h = threadIdx.x;
    if (blockIdx.y == 0) {
        float acc = 0.f;
        for (int k = 0; k < INP; k++) {
            float w  = W_sa[((long)a * INP + k) * HID + h];
            float is = istd[a * INP + k];
            float m  = mean[a * INP + k];
            Wsaf[((long)a * INP + k) * HID + h] = w * is;
            acc += m * is * w;
        }
        b1[a * 256 + h] = b_sa[a * HID + h] - acc;
    } else {
        float acc = 0.f;
        for (int k = 0; k < OBS; k++) {
            float w  = W_s[((long)a * OBS + k) * HID + h];
            float is = istd[a * INP + k];
            float m  = mean[a * INP + k];
            Wsf[((long)a * OBS + k) * HID + h] = w * is;
            acc += m * is * w;
        }
        b1[a * 256 + 128 + h] = b_s[a * HID + h] - acc;
    }
}

// ---------------- build all bf16 hi/lo weight images ---------------------------
__global__ void prep_kernel(const float* __restrict__ Wsaf, const float* __restrict__ Wsf,
                            const float* __restrict__ Wk, const float* __restrict__ Wsel,
                            const float* __restrict__ Wv, const float* __restrict__ bv,
                            const float* __restrict__ Wc1,
                            __nv_bfloat16* __restrict__ w1h, __nv_bfloat16* __restrict__ w1l,
                            __nv_bfloat16* __restrict__ kvh, __nv_bfloat16* __restrict__ kvl,
                            __nv_bfloat16* __restrict__ selh, __nv_bfloat16* __restrict__ sell,
                            __nv_bfloat16* __restrict__ c1h, __nv_bfloat16* __restrict__ c1l,
                            float* __restrict__ bkv)
{
    int img = blockIdx.y;
    int a = blockIdx.z;
    int e = blockIdx.x * 256 + threadIdx.x;
    float v;
    __nv_bfloat16* hp;
    __nv_bfloat16* lp;
    long dst;

    if (img == 0) {
        if (e >= 256 * INP) return;
        int n = e / INP, k = e - n * INP;
        if (n < 128) v = Wsaf[((long)a * INP + k) * HID + n];
        else         v = (k < OBS) ? Wsf[((long)a * OBS + k) * HID + (n - 128)] : 0.f;
        hp = w1h; lp = w1l; dst = (long)a * 256 * INP + e;
    } else if (img == 1) {
        if (a != 0) return;
        if (e >= 256 * HID) return;
        int n = e / HID, k = e - n * HID;
        if (n < 128) v = Wk[(((n >> 5) * HID) + k) * DHEAD + (n & 31)];
        else {
            int n2 = n - 128;
            v = Wv[(((n2 >> 5) * HID) + k) * DHEAD + (n2 & 31)];
        }
        if (e < 256) bkv[e] = (e < 128) ? 0.f : bv[e - 128];
        hp = kvh; lp = kvl; dst = e;
    } else if (img == 2) {
        if (a != 0) return;
        if (e >= HID * HID) return;
        int n = e / HID, k = e - n * HID;
        v = Wsel[(((n >> 5) * HID) + k) * DHEAD + (n & 31)];
        hp = selh; lp = sell; dst = e;
    } else {
        if (e >= HID * 2 * HID) return;
        int n = e / (2 * HID), k = e - n * (2 * HID);
        v = Wc1[((long)a * 2 * HID + k) * HID + n];
        hp = c1h; lp = c1l; dst = (long)a * HID * 2 * HID + e;
    }
    __nv_bfloat16 h = __float2bfloat16(v);
    __nv_bfloat16 l = __float2bfloat16(v - __bfloat162float(h));
    hp[dst] = h;
    lp[dst] = l;
}

// ---------------- tensor-core GEMM via mma.sync (bf16x3, pure-copy loads) -----
// A given as bf16 hi/lo planes (A0, optional A1 concat at ksplit).
// Output modes: fp32 C (default), bf16-pair (outBf16), fused final (fuseFinal).
// mergedSel: blockIdx.y==2 switches to (A +128 cols, B2 image, C2 output).
__global__ void __launch_bounds__(256, 2) gemm_mma(
    const __nv_bfloat16* __restrict__ A0h, const __nv_bfloat16* __restrict__ A0l,
    long sA0, int lda0,
    const __nv_bfloat16* __restrict__ A1h, const __nv_bfloat16* __restrict__ A1l,
    long sA1, int lda1, int ksplit,
    const __nv_bfloat16* __restrict__ Bhi, const __nv_bfloat16* __restrict__ Blo,
    long sB, int Ktot, int chunkK,
    const float* __restrict__ bias, long sBias,
    float* __restrict__ C, long sC, int ldc, int actFrom,
    int outBf16, __nv_bfloat16* __restrict__ Ch, __nv_bfloat16* __restrict__ Cl,
    int mergedSel, const __nv_bfloat16* __restrict__ B2h, const __nv_bfloat16* __restrict__ B2l,
    float* __restrict__ C2, long sC2,
    int fuseFinal, const float* __restrict__ actions, const float* __restrict__ Wc2,
    const float* __restrict__ bc2, float* __restrict__ outq)
{
    extern __shared__ __nv_bfloat16 sm[];
    __shared__ float sWc2[HID * ACT];
    __shared__ int   sIdx[128];
    __shared__ float sQred[2][128];

    const int stride = chunkK + 8;
    __nv_bfloat16* Ah = sm;
    __nv_bfloat16* Al = Ah + 128 * stride;
    __nv_bfloat16* Bh = Al + 128 * stride;
    __nv_bfloat16* Bl = Bh + 128 * stride;

    int tid = threadIdx.x, wid = tid >> 5, lane = tid & 31;
    int a = blockIdx.z;
    long mBase = (long)blockIdx.x * 128;
    int wm = (wid & 3) * 32;
    int wn = (wid >> 2) * 64;

    // per-y routing
    int colBase = blockIdx.y * 128;
    int aOff = 0;
    const __nv_bfloat16* bhP = Bhi;
    const __nv_bfloat16* blP = Blo;
    float* Cout = C;
    long sCout = sC;
    int ldcL = ldc;
    const float* biasL = bias;
    int actF = actFrom;
    if (mergedSel && blockIdx.y == 2) {
        aOff = 128; bhP = B2h; blP = B2l; colBase = 0;
        Cout = C2; sCout = sC2; ldcL = 128; biasL = nullptr; actF = 1 << 30;
    }
    bhP += (long)a * sB;
    blP += (long)a * sB;

    if (fuseFinal) {
        for (int i = tid; i < HID * ACT; i += 256)
            sWc2[i] = Wc2[(long)a * HID * ACT + i];
        if (tid < 128) {
            const float* ap = actions + ((long)a * BATCH + mBase + tid) * ACT;
            float best = ap[0]; int bi = 0;
#pragma unroll
            for (int j = 1; j < ACT; j++) {
                float x = ap[j];
                if (x > best) { best = x; bi = j; }
            }
            sIdx[tid] = bi;
        }
    }

    float acc[2][8][4];
#pragma unroll
    for (int i = 0; i < 2; i++)
#pragma unroll
        for (int j = 0; j < 8; j++)
#pragma unroll
            for (int q = 0; q < 4; q++) acc[i][j][q] = 0.f;

    int nChunks = Ktot / chunkK;
    int kq8 = chunkK >> 3;
    uint32_t AhB = smem_u32(Ah), AlB = smem_u32(Al);
    uint32_t BhB = smem_u32(Bh), BlB = smem_u32(Bl);

    for (int c = 0; c < nChunks; c++) {
        if (c > 0) __syncthreads();
        int k0 = c * chunkK;

        // ---- cp.async A chunk (bf16 pair planes) ----
        for (int i = tid; i < 128 * kq8; i += 256) {
            int row = i / kq8;
            int kk = (i - row * kq8) * 8;
            int kg = k0 + kk;
            const __nv_bfloat16 *ph, *pl;
            if (kg < ksplit) {
                long o = (long)a * sA0 + (mBase + row) * (long)lda0 + aOff + kg;
                ph = A0h + o; pl = A0l + o;
            } else {
                long o = (long)a * sA1 + (mBase + row) * (long)lda1 + (kg - ksplit);
                ph = A1h + o; pl = A1l + o;
            }
            uint32_t d = (uint32_t)((row * stride + kk) * 2);
            cp16(AhB + d, ph);
            cp16(AlB + d, pl);
        }
        // ---- cp.async B chunk ----
        for (int i = tid; i < 128 * kq8; i += 256) {
            int n = i / kq8;
            int kk = (i - n * kq8) * 8;
            long o = (long)(colBase + n) * Ktot + k0 + kk;
            uint32_t d = (uint32_t)((n * stride + kk) * 2);
            cp16(BhB + d, bhP + o);
            cp16(BlB + d, blP + o);
        }
        cp_wait();
        __syncthreads();

        // ---- compute ----
        int lr16 = lane & 15, lh16 = (lane >> 4) * 8;
        int lr8 = lane & 7, lk8 = ((lane >> 3) & 1) * 8, ln8 = (lane >> 4) * 8;

        for (int ks = 0; ks < chunkK; ks += 16) {
            uint32_t ah[2][4], al[2][4];
#pragma unroll
            for (int mi = 0; mi < 2; mi++) {
                uint32_t addr = AhB + (uint32_t)(((wm + mi * 16 + lr16) * stride + ks + lh16) * 2);
                ldm_x4(ah[mi], addr);
                addr = AlB + (uint32_t)(((wm + mi * 16 + lr16) * stride + ks + lh16) * 2);
                ldm_x4(al[mi], addr);
            }
#pragma unroll
            for (int ni4 = 0; ni4 < 4; ni4++) {
                int n0 = wn + ni4 * 16;
                uint32_t boff = (uint32_t)(((n0 + ln8 + lr8) * stride + ks + lk8) * 2);
                uint32_t bh[4], bl[4];
                ldm_x4(bh, BhB + boff);
                ldm_x4(bl, BlB + boff);
#pragma unroll
                for (int mi = 0; mi < 2; mi++) {
                    mma_bf16(acc[mi][ni4 * 2],     ah[mi], bh[0], bh[1]);
                    mma_bf16(acc[mi][ni4 * 2 + 1], ah[mi], bh[2], bh[3]);
                    mma_bf16(acc[mi][ni4 * 2],     ah[mi], bl[0], bl[1]);
                    mma_bf16(acc[mi][ni4 * 2 + 1], ah[mi], bl[2], bl[3]);
                    mma_bf16(acc[mi][ni4 * 2],     al[mi], bh[0], bh[1]);
                    mma_bf16(acc[mi][ni4 * 2 + 1], al[mi], bh[2], bh[3]);
                }
            }
        }
    }

    // ---- epilogue ----
    int gr = lane >> 2, tg = lane & 3;

    if (fuseFinal) {
        float p[4] = {0.f, 0.f, 0.f, 0.f};
#pragma unroll
        for (int mi = 0; mi < 2; mi++) {
            int ra = wm + mi * 16 + gr;
            int rb = ra + 8;
            int ia = sIdx[ra], ib = sIdx[rb];
#pragma unroll
            for (int ni = 0; ni < 8; ni++) {
                int col = wn + ni * 8 + tg * 2;
                const float* bp = biasL + (long)a * sBias + col;
                float b0 = bp[0], b1 = bp[1];
                float v0 = acc[mi][ni][0] + b0;
                float v1 = acc[mi][ni][1] + b1;
                float v2 = acc[mi][ni][2] + b0;
                float v3 = acc[mi][ni][3] + b1;
                v0 = v0 > 0.f ? v0 : 0.01f * v0;
                v1 = v1 > 0.f ? v1 : 0.01f * v1;
                v2 = v2 > 0.f ? v2 : 0.01f * v2;
                v3 = v3 > 0.f ? v3 : 0.01f * v3;
                p[mi * 2]     += v0 * sWc2[col * ACT + ia] + v1 * sWc2[(col + 1) * ACT + ia];
                p[mi * 2 + 1] += v2 * sWc2[col * ACT + ib] + v3 * sWc2[(col + 1) * ACT + ib];
            }
        }
#pragma unroll
        for (int q = 0; q < 4; q++) {
            p[q] += __shfl_xor_sync(0xffffffffu, p[q], 1);
            p[q] += __shfl_xor_sync(0xffffffffu, p[q], 2);
        }
        int nh = wid >> 2;
        if (tg == 0) {
            sQred[nh][wm + gr]      = p[0];
            sQred[nh][wm + gr + 8]  = p[1];
            sQred[nh][wm + gr + 16] = p[2];
            sQred[nh][wm + gr + 24] = p[3];
        }
        __syncthreads();
        if (tid < 128) {
            float q = sQred[0][tid] + sQred[1][tid] + bc2[a * ACT + sIdx[tid]];
            outq[(long)a * BATCH + mBase + tid] = q;
        }
        return;
    }

#pragma unroll
    for (int mi = 0; mi < 2; mi++) {
        long row0 = mBase + wm + mi * 16 + gr;
        long row1 = row0 + 8;
#pragma unroll
        for (int ni = 0; ni < 8; ni++) {
            int col = colBase + wn + ni * 8 + tg * 2;
            float b0 = 0.f, b1 = 0.f;
            if (biasL) {
                const float* bp = biasL + (long)a * sBias + col;
                b0 = bp[0]; b1 = bp[1];
            }
            float v0 = acc[mi][ni][0] + b0;
            float v1 = acc[mi][ni][1] + b1;
            float v2 = acc[mi][ni][2] + b0;
            float v3 = acc[mi][ni][3] + b1;
            if (col >= actF) {
                v0 = v0 > 0.f ? v0 : 0.01f * v0;
                v2 = v2 > 0.f ? v2 : 0.01f * v2;
            }
            if (col + 1 >= actF) {
                v1 = v1 > 0.f ? v1 : 0.01f * v1;
                v3 = v3 > 0.f ? v3 : 0.01f * v3;
            }
            if (outBf16) {
                long o0 = (long)a * sCout + row0 * ldcL + col;
                long o1 = (long)a * sCout + row1 * ldcL + col;
                __nv_bfloat16 h0 = __float2bfloat16(v0), h1 = __float2bfloat16(v1);
                __nv_bfloat16 h2 = __float2bfloat16(v2), h3 = __float2bfloat16(v3);
                *(uint32_t*)(Ch + o0) = (uint32_t)__bfloat16_as_ushort(h0) |
                                        ((uint32_t)__bfloat16_as_ushort(h1) << 16);
                *(uint32_t*)(Ch + o1) = (uint32_t)__bfloat16_as_ushort(h2) |
                                        ((uint32_t)__bfloat16_as_ushort(h3) << 16);
                *(uint32_t*)(Cl + o0) = pack_bf16(v0 - __bfloat162float(h0),
                                                  v1 - __bfloat162float(h1));
                *(uint32_t*)(Cl + o1) = pack_bf16(v2 - __bfloat162float(h2),
                                                  v3 - __bfloat162float(h3));
            } else {
                float* Cp = Cout + (long)a * sCout;
                *(float2*)(Cp + row0 * ldcL + col) = make_float2(v0, v1);
                *(float2*)(Cp + row1 * ldcL + col) = make_float2(v2, v3);
            }
        }
    }
}

// ---------------- attention: one warp per (head, agent_i, batch) --------------
__global__ void attn_kernel(const float* __restrict__ KV, const float* __restrict__ St,
                            __nv_bfloat16* __restrict__ oH, __nv_bfloat16* __restrict__ oL)
{
    int gw   = blockIdx.x * 8 + (threadIdx.x >> 5);
    int lane = threadIdx.x & 31;
    int b = gw >> 6;
    int r = gw & 63;
    int n = r >> 4;
    int i = r & 15;
    int col = n * DHEAD + lane;

    float selv = St[((long)i * BATCH + b) * HID + col];
    float lg = -3e38f;
#pragma unroll
    for (int j = 0; j < 16; j++) {
        float p = selv * KV[((long)j * BATCH + b) * 256 + col];
#pragma unroll
        for (int off = 16; off; off >>= 1) p += __shfl_xor_sync(0xffffffffu, p, off);
        if (lane == j) lg = (j == i) ? -1e9f : p * 0.17677669529663687f;
    }
    float mx = lg;
#pragma unroll
    for (int off = 16; off; off >>= 1) mx = fmaxf(mx, __shfl_xor_sync(0xffffffffu, mx, off));
    float e = (lane < 16) ? __expf(lg - mx) : 0.f;
    float den = e;
#pragma unroll
    for (int off = 16; off; off >>= 1) den += __shfl_xor_sync(0xffffffffu, den, off);
    float w = e / den;

    float acc = 0.f;
#pragma unroll
    for (int j = 0; j < 16; j++) {
        float wj = __shfl_sync(0xffffffffu, w, j);
        acc = fmaf(wj, KV[((long)j * BATCH + b) * 256 + 128 + col], acc);
    }
    long o = ((long)i * BATCH + b) * HID + col;
    __nv_bfloat16 h = __float2bfloat16(acc);
    oH[o] = h;
    oL[o] = __float2bfloat16(acc - __bfloat162float(h));
}

// ---------------- launch -------------------------------------------------------
static float* symaddr(const void* sym)
{
    void* p = nullptr;
    cudaGetSymbolAddress(&p, sym);
    return (float*)p;
}
static __nv_bfloat16* symaddr_bf(const void* sym)
{
    void* p = nullptr;
    cudaGetSymbolAddress(&p, sym);
    return (__nv_bfloat16*)p;
}

extern "C" void kernel_launch(void* const* d_in, const int* in_sizes, int n_in,
                              void* d_out, int out_size)
{
    const float* obs     = (const float*)d_in[0];
    const float* actions = (const float*)d_in[1];
    const float* W_sa    = (const float*)d_in[2];
    const float* b_sa    = (const float*)d_in[3];
    const float* W_s     = (const float*)d_in[4];
    const float* b_s     = (const float*)d_in[5];
    const float* Wk      = (const float*)d_in[6];
    const float* Wsel    = (const float*)d_in[7];
    const float* Wv      = (const float*)d_in[8];
    const float* bv      = (const float*)d_in[9];
    const float* Wc1     = (const float*)d_in[10];
    const float* bc1     = (const float*)d_in[11];
    const float* Wc2     = (const float*)d_in[12];
    const float* bc2     = (const float*)d_in[13];
    float* out = (float*)d_out;

    float* ps    = symaddr(g_ps);
    float* ps2   = symaddr(g_ps2);
    float* mean  = symaddr(g_mean);
    float* istd  = symaddr(g_istd);
    float* Wsaf  = symaddr(g_Wsaf);
    float* Wsf   = symaddr(g_Wsf);
    float* b1    = symaddr(g_b1);
    float* bkv   = symaddr(g_bkv);
    float* KV    = symaddr(g_KV);
    float* St    = symaddr(g_S);

    __nv_bfloat16* w1h  = symaddr_bf(w1_hi);
    __nv_bfloat16* w1l  = symaddr_bf(w1_lo);
    __nv_bfloat16* kvh  = symaddr_bf(wkv_hi);
    __nv_bfloat16* kvl  = symaddr_bf(wkv_lo);
    __nv_bfloat16* selh = symaddr_bf(wsel_hi);
    __nv_bfloat16* sell = symaddr_bf(wsel_lo);
    __nv_bfloat16* c1h  = symaddr_bf(wc1_hi);
    __nv_bfloat16* c1l  = symaddr_bf(wc1_lo);
    __nv_bfloat16* obsH = symaddr_bf(g_obsH);
    __nv_bfloat16* obsL = symaddr_bf(g_obsL);
    __nv_bfloat16* actH = symaddr_bf(g_actH);
    __nv_bfloat16* actL = symaddr_bf(g_actL);
    __nv_bfloat16* aseH = symaddr_bf(g_aseH);
    __nv_bfloat16* aseL = symaddr_bf(g_aseL);
    __nv_bfloat16* othH = symaddr_bf(g_othH);
    __nv_bfloat16* othL = symaddr_bf(g_othL);

    static bool attr_set = false;
    if (!attr_set) {
        cudaFuncSetAttribute(gemm_mma, cudaFuncAttributeMaxDynamicSharedMemorySize, 100000);
        attr_set = true;
    }

    bn_part_kernel<<<dim3(AGENTS, 5, 8), dim3(32, 32)>>>(obs, actions, ps, ps2,
                                                          obsH, obsL, actH, actL);
    bn_fin_kernel<<<AGENTS, 160>>>(ps, ps2, mean, istd);
    fold_kernel<<<dim3(AGENTS, 2), HID>>>(W_sa, b_sa, W_s, b_s, mean, istd, Wsaf, Wsf, b1);
    prep_kernel<<<dim3(144, 4, AGENTS), 256>>>(Wsaf, Wsf, Wk, Wsel, Wv, bv, Wc1,
                                               w1h, w1l, kvh, kvl, selh, sell, c1h, c1l, bkv);

    const long sOBS = (long)BATCH * OBS;
    const long sACT = (long)BATCH * ACT;
    const long sASE = (long)BATCH * 256;
    const long sH   = (long)BATCH * HID;

    size_t smem48 = 4 * (size_t)128 * (48 + 8) * 2;
    size_t smem64 = 4 * (size_t)128 * (64 + 8) * 2;

    // 4: ase(bf16 pair) = lrelu(bn([obs|act]) @ [W_sa|W_s] + b1)  K=144, N=256
    gemm_mma<<<dim3(BATCH / 128, 2, AGENTS), 256, smem48>>>(
        obsH, obsL, sOBS, OBS, actH, actL, sACT, ACT, OBS,
        w1h, w1l, (long)256 * INP, INP, 48,
        b1, 256, nullptr, sASE, 256, 0,
        1, aseH, aseL,
        0, nullptr, nullptr, nullptr, 0,
        0, nullptr, nullptr, nullptr, nullptr);

    // 5 (profiled): merged KV + Sel.  y<2: KV = sa @ [Wk|Wv]; y==2: S = se @ Wsel
    gemm_mma<<<dim3(BATCH / 128, 3, AGENTS), 256, smem64>>>(
        aseH, aseL, sASE, 256, nullptr, nullptr, 0, 0, 1 << 30,
        kvh, kvl, 0, HID, 64,
        bkv, 0, KV, sASE, 256, 128,
        0, nullptr, nullptr,
        1, selh, sell, St, sH,
        0, nullptr, nullptr, nullptr, nullptr);

    // 6: attention -> other (bf16 pair)
    attn_kernel<<<(BATCH * 64) / 8, 256>>>(KV, St, othH, othL);

    // 7: q = fused( lrelu([se|other] @ Wc1 + bc1) . Wc2[:,argmax] + bc2 )  K=256
    gemm_mma<<<dim3(BATCH / 128, 1, AGENTS), 256, smem64>>>(
        aseH + 128, aseL + 128, sASE, 256, othH, othL, sH, HID, HID,
        c1h, c1l, (long)HID * 2 * HID, 2 * HID, 64,
        bc1, HID, nullptr, 0, 0, 1 << 30,
        0, nullptr, nullptr,
        0, nullptr, nullptr, nullptr, 0,
        1, actions, Wc2, bc2, out);
}

// round 8
// speedup vs baseline: 3.3177x; 1.1745x over previous
#include <cuda_runtime.h>
#include <cuda_fp16.h>
#include <cstdint>

#define AGENTS 16
#define BATCH  8192
#define OBS    128
#define ACT    16
#define HID    128
#define NHEAD  4
#define DHEAD  32
#define INP    (OBS + ACT)   // 144

#define CHUNK  32
#define STRIDE (CHUNK + 8)   // 40
#define PLANE  (128 * STRIDE)

// ---------------- scratch (static device globals; no runtime alloc) -----------
__device__ float g_ps [AGENTS * 160 * 8];
__device__ float g_ps2[AGENTS * 160 * 8];
__device__ float g_mean[AGENTS * INP];
__device__ float g_istd[AGENTS * INP];
__device__ float g_b1  [AGENTS * 256];       // [bsaf | bsf]
__device__ float g_bkv [256];                // [0 | bv]
// fp16 weight images (hi only), [n][Kpad] row-major (B^T)
__device__ __half w1_h [(long)AGENTS * 256 * 160];
__device__ __half wkv_h[256 * HID];
__device__ __half wsel_h[HID * HID];
__device__ __half wc1_h[(long)AGENTS * HID * 2 * HID];
// fp16 hi/lo activation planes
__device__ __half g_obsH[(long)AGENTS * BATCH * OBS];
__device__ __half g_obsL[(long)AGENTS * BATCH * OBS];
__device__ __half g_actH[(long)AGENTS * BATCH * ACT];
__device__ __half g_actL[(long)AGENTS * BATCH * ACT];
__device__ __half g_aseH[(long)AGENTS * BATCH * 256];   // [sa | se]
__device__ __half g_aseL[(long)AGENTS * BATCH * 256];
__device__ __half g_othH[(long)AGENTS * BATCH * HID];
__device__ __half g_othL[(long)AGENTS * BATCH * HID];
// fp32 buffers for attention inputs
__device__ float g_KV   [(long)AGENTS * BATCH * 256];   // [K | V]
__device__ float g_S    [(long)AGENTS * BATCH * HID];

// ---------------- helpers ------------------------------------------------------
__device__ __forceinline__ uint32_t smem_u32(const void* p) {
    uint32_t r;
    asm("{ .reg .u64 t; cvta.to.shared.u64 t, %1; cvt.u32.u64 %0, t; }" : "=r"(r) : "l"(p));
    return r;
}
__device__ __forceinline__ void ldm_x4(uint32_t* r, uint32_t addr) {
    asm volatile("ldmatrix.sync.aligned.m8n8.x4.shared.b16 {%0,%1,%2,%3}, [%4];"
                 : "=r"(r[0]), "=r"(r[1]), "=r"(r[2]), "=r"(r[3]) : "r"(addr));
}
__device__ __forceinline__ void mma_f16(float* c, const uint32_t* a, uint32_t b0, uint32_t b1) {
    asm volatile("mma.sync.aligned.m16n8k16.row.col.f32.f16.f16.f32 "
                 "{%0,%1,%2,%3}, {%4,%5,%6,%7}, {%8,%9}, {%0,%1,%2,%3};"
                 : "+f"(c[0]), "+f"(c[1]), "+f"(c[2]), "+f"(c[3])
                 : "r"(a[0]), "r"(a[1]), "r"(a[2]), "r"(a[3]), "r"(b0), "r"(b1));
}
__device__ __forceinline__ void cp16(uint32_t dst, const void* src) {
    asm volatile("cp.async.cg.shared.global [%0], [%1], 16;" :: "r"(dst), "l"(src));
}
__device__ __forceinline__ void cp16p(uint32_t dst, const void* src, int ok) {
    asm volatile("{\n\t.reg .pred p;\n\tsetp.ne.b32 p, %2, 0;\n\t"
                 "@p cp.async.cg.shared.global [%0], [%1], 16;\n\t"
                 "@!p cp.async.cg.shared.global [%0], [%1], 16, 0;\n\t}"
                 :: "r"(dst), "l"(src), "r"(ok));
}
__device__ __forceinline__ void cp_commit() { asm volatile("cp.async.commit_group;" ::: "memory"); }
__device__ __forceinline__ void cp_wait1()  { asm volatile("cp.async.wait_group 1;" ::: "memory"); }
__device__ __forceinline__ void cp_wait0()  { asm volatile("cp.async.wait_group 0;" ::: "memory"); }
__device__ __forceinline__ uint32_t pack_h2(float x, float y) {
    __half hx = __float2half_rn(x), hy = __float2half_rn(y);
    return (uint32_t)__half_as_ushort(hx) | ((uint32_t)__half_as_ushort(hy) << 16);
}

// ---------------- BN pass 1: partial sums + fp16 split planes ------------------
__global__ void bn_part_kernel(const float* __restrict__ obs,
                               const float* __restrict__ actions,
                               float* __restrict__ ps, float* __restrict__ ps2,
                               __half* __restrict__ oH, __half* __restrict__ oL,
                               __half* __restrict__ aH, __half* __restrict__ aL)
{
    int a = blockIdx.x;
    int f = blockIdx.y * 32 + threadIdx.x;
    int seg = blockIdx.z;
    float s = 0.f, s2 = 0.f;
    if (f < INP) {
        if (f < OBS) {
            long base = (long)a * BATCH * OBS + (long)seg * 1024 * OBS + f;
            const float* src = obs + base;
            for (int b = threadIdx.y; b < 1024; b += 32) {
                float x = src[(long)b * OBS]; s += x; s2 += x * x;
                __half h = __float2half_rn(x);
                oH[base + (long)b * OBS] = h;
                oL[base + (long)b * OBS] = __float2half_rn(x - __half2float(h));
            }
        } else {
            long base = (long)a * BATCH * ACT + (long)seg * 1024 * ACT + (f - OBS);
            const float* src = actions + base;
            for (int b = threadIdx.y; b < 1024; b += 32) {
                float x = src[(long)b * ACT]; s += x; s2 += x * x;
                __half h = __float2half_rn(x);
                aH[base + (long)b * ACT] = h;
                aL[base + (long)b * ACT] = __float2half_rn(x - __half2float(h));
            }
        }
    }
    __shared__ float sh1[32][33];
    __shared__ float sh2[32][33];
    sh1[threadIdx.y][threadIdx.x] = s;
    sh2[threadIdx.y][threadIdx.x] = s2;
    __syncthreads();
    for (int st = 16; st > 0; st >>= 1) {
        if (threadIdx.y < st) {
            sh1[threadIdx.y][threadIdx.x] += sh1[threadIdx.y + st][threadIdx.x];
            sh2[threadIdx.y][threadIdx.x] += sh2[threadIdx.y + st][threadIdx.x];
        }
        __syncthreads();
    }
    if (threadIdx.y == 0) {
        int fi = blockIdx.y * 32 + threadIdx.x;
        ps [(a * 160 + fi) * 8 + seg] = sh1[0][threadIdx.x];
        ps2[(a * 160 + fi) * 8 + seg] = sh2[0][threadIdx.x];
    }
}

// ---------------- BN pass 2 -----------------------------------------------------
__global__ void bn_fin_kernel(const float* __restrict__ ps, const float* __restrict__ ps2,
                              float* __restrict__ mean, float* __restrict__ istd)
{
    int a = blockIdx.x;
    int f = threadIdx.x;
    if (f >= INP) return;
    float s = 0.f, s2 = 0.f;
    for (int seg = 0; seg < 8; seg++) {
        s  += ps [(a * 160 + f) * 8 + seg];
        s2 += ps2[(a * 160 + f) * 8 + seg];
    }
    float m = s * (1.0f / BATCH);
    float v = s2 * (1.0f / BATCH) - m * m;
    mean[a * INP + f] = m;
    istd[a * INP + f] = rsqrtf(v + 1e-5f);
}

// ---------------- prep_all: BN-folded fp16 weight images + biases --------------
// y=0: W1 [256][160]; y=1: KV [256][128]; y=2: Sel [128][128]; y=3: C1 [128][256];
// y=4: b1 / bkv reductions.
__global__ void prep_all(const float* __restrict__ W_sa, const float* __restrict__ b_sa,
                         const float* __restrict__ W_s,  const float* __restrict__ b_s,
                         const float* __restrict__ Wk, const float* __restrict__ Wsel,
                         const float* __restrict__ Wv, const float* __restrict__ bv,
                         const float* __restrict__ Wc1,
                         const float* __restrict__ mean, const float* __restrict__ istd,
                         __half* __restrict__ w1h, __half* __restrict__ kvh,
                         __half* __restrict__ selh, __half* __restrict__ c1h,
                         float* __restrict__ b1, float* __restrict__ bkv)
{
    int img = blockIdx.y;
    int a = blockIdx.z;
    int e = blockIdx.x * 256 + threadIdx.x;

    if (img == 0) {
        if (e >= 256 * 160) return;
        int n = e / 160, k = e - n * 160;
        float v = 0.f;
        if (n < 128) { if (k < INP) v = W_sa[((long)a * INP + k) * HID + n] * istd[a * INP + k]; }
        else         { if (k < OBS) v = W_s [((long)a * OBS + k) * HID + (n - 128)] * istd[a * INP + k]; }
        w1h[(long)a * 256 * 160 + e] = __float2half_rn(v);
    } else if (img == 1) {
        if (a != 0 || e >= 256 * 128) return;
        int n = e >> 7, k = e & 127;
        float v = (n < 128) ? Wk[(((n >> 5) * HID) + k) * DHEAD + (n & 31)]
                            : Wv[((((n - 128) >> 5) * HID) + k) * DHEAD + ((n - 128) & 31)];
        kvh[e] = __float2half_rn(v);
    } else if (img == 2) {
        if (a != 0 || e >= 128 * 128) return;
        int n = e >> 7, k = e & 127;
        selh[e] = __float2half_rn(Wsel[(((n >> 5) * HID) + k) * DHEAD + (n & 31)]);
    } else if (img == 3) {
        if (e >= 128 * 256) return;
        int n = e >> 8, k = e & 255;
        c1h[(long)a * 128 * 256 + e] = __float2half_rn(Wc1[((long)a * 2 * HID + k) * HID + n]);
    } else {
        if (blockIdx.x != 0) return;
        int n = threadIdx.x;   // 0..255
        float acc = 0.f;
        if (n < 128) {
            for (int k = 0; k < INP; k++)
                acc += mean[a * INP + k] * istd[a * INP + k] * W_sa[((long)a * INP + k) * HID + n];
            b1[a * 256 + n] = b_sa[a * HID + n] - acc;
        } else {
            for (int k = 0; k < OBS; k++)
                acc += mean[a * INP + k] * istd[a * INP + k] * W_s[((long)a * OBS + k) * HID + (n - 128)];
            b1[a * 256 + n] = b_s[a * HID + (n - 128)] - acc;
        }
        if (a == 0) bkv[n] = (n < 128) ? 0.f : bv[n - 128];
    }
}

// ---------------- tensor-core GEMM (fp16 2-term split, fp32 accum) -------------
// C[m,n] = act( sum_k (Ah+Al)[m,k] * Bh[n,k] + bias[n] )
// A planes fp16 hi/lo; B fp16 hi only. 2-stage cp.async pipeline, chunk=32.
__global__ void __launch_bounds__(256, 2) gemm_mma(
    const __half* __restrict__ A0h, const __half* __restrict__ A0l, long sA0, int lda0,
    const __half* __restrict__ A1h, const __half* __restrict__ A1l, long sA1, int lda1,
    int ksplit, int Kreal,
    const __half* __restrict__ Bh_, long sB, int Kpad,
    const float* __restrict__ bias, long sBias,
    float* __restrict__ C, long sC, int ldc, int actFrom,
    int outHalf, __half* __restrict__ Ch, __half* __restrict__ Cl,
    int mergedSel, const __half* __restrict__ B2h, float* __restrict__ C2, long sC2,
    int fuseFinal, const float* __restrict__ actions, const float* __restrict__ Wc2,
    const float* __restrict__ bc2, float* __restrict__ outq)
{
    extern __shared__ __half sm[];
    __shared__ float sWc2[HID * ACT];
    __shared__ int   sIdx[128];
    __shared__ float sQred[2][128];

    int tid = threadIdx.x, wid = tid >> 5, lane = tid & 31;
    int a = blockIdx.z;
    long mBase = (long)blockIdx.x * 128;
    int wm = (wid & 3) * 32;
    int wn = (wid >> 2) * 64;

    // per-y routing
    int colBase = blockIdx.y * 128;
    int aOff = 0;
    const __half* bhP = Bh_;
    float* Cout = C;
    long sCout = sC;
    int ldcL = ldc;
    const float* biasL = bias;
    int actF = actFrom;
    if (mergedSel && blockIdx.y == 2) {
        aOff = 128; bhP = B2h; colBase = 0;
        Cout = C2; sCout = sC2; ldcL = 128; biasL = nullptr; actF = 1 << 30;
    }
    bhP += (long)a * sB;

    if (fuseFinal) {
        for (int i = tid; i < HID * ACT; i += 256)
            sWc2[i] = Wc2[(long)a * HID * ACT + i];
        if (tid < 128) {
            const float* ap = actions + ((long)a * BATCH + mBase + tid) * ACT;
            float best = ap[0]; int bi = 0;
#pragma unroll
            for (int j = 1; j < ACT; j++) {
                float x = ap[j];
                if (x > best) { best = x; bi = j; }
            }
            sIdx[tid] = bi;
        }
    }

    float acc[2][8][4];
#pragma unroll
    for (int i = 0; i < 2; i++)
#pragma unroll
        for (int j = 0; j < 8; j++)
#pragma unroll
            for (int q = 0; q < 4; q++) acc[i][j][q] = 0.f;

    uint32_t smB = smem_u32(sm);
    int nChunks = Kpad / CHUNK;

    auto issue = [&](int c, int buf) {
        uint32_t base = smB + (uint32_t)(buf * 3 * PLANE * 2);
        uint32_t AhB = base, AlB = base + PLANE * 2, BhB = base + 2 * PLANE * 2;
        int k0 = c * CHUNK;
        // A: 128 rows x 4 quads, both planes
        for (int i = tid; i < 512; i += 256) {
            int row = i >> 2, kk = (i & 3) * 8;
            int kg = k0 + kk;
            const __half *ph, *pl; int ok = 1;
            if (kg < ksplit) {
                long o = (long)a * sA0 + (mBase + row) * (long)lda0 + aOff + kg;
                ph = A0h + o; pl = A0l + o;
            } else if (kg < Kreal) {
                long o = (long)a * sA1 + (mBase + row) * (long)lda1 + (kg - ksplit);
                ph = A1h + o; pl = A1l + o;
            } else {
                ph = A0h; pl = A0l; ok = 0;
            }
            uint32_t d = (uint32_t)((row * STRIDE + kk) * 2);
            cp16p(AhB + d, ph, ok);
            cp16p(AlB + d, pl, ok);
        }
        // B: 128 rows x 4 quads
        for (int i = tid; i < 512; i += 256) {
            int n = i >> 2, kk = (i & 3) * 8;
            long o = (long)(colBase + n) * Kpad + k0 + kk;
            cp16(BhB + (uint32_t)((n * STRIDE + kk) * 2), bhP + o);
        }
        cp_commit();
    };

    issue(0, 0);
    int lr16 = lane & 15, lh16 = (lane >> 4) * 8;
    int lr8 = lane & 7, lk8 = ((lane >> 3) & 1) * 8, ln8 = (lane >> 4) * 8;

    for (int c = 0; c < nChunks; c++) {
        if (c + 1 < nChunks) { issue(c + 1, (c + 1) & 1); cp_wait1(); }
        else                 { cp_wait0(); }
        __syncthreads();

        uint32_t base = smB + (uint32_t)((c & 1) * 3 * PLANE * 2);
        uint32_t AhB = base, AlB = base + PLANE * 2, BhB = base + 2 * PLANE * 2;

#pragma unroll
        for (int ks = 0; ks < CHUNK; ks += 16) {
            uint32_t ah[2][4], al[2][4];
#pragma unroll
            for (int mi = 0; mi < 2; mi++) {
                uint32_t addr = AhB + (uint32_t)(((wm + mi * 16 + lr16) * STRIDE + ks + lh16) * 2);
                ldm_x4(ah[mi], addr);
                addr = AlB + (uint32_t)(((wm + mi * 16 + lr16) * STRIDE + ks + lh16) * 2);
                ldm_x4(al[mi], addr);
            }
#pragma unroll
            for (int ni4 = 0; ni4 < 4; ni4++) {
                int n0 = wn + ni4 * 16;
                uint32_t boff = (uint32_t)(((n0 + ln8 + lr8) * STRIDE + ks + lk8) * 2);
                uint32_t bh[4];
                ldm_x4(bh, BhB + boff);
#pragma unroll
                for (int mi = 0; mi < 2; mi++) {
                    mma_f16(acc[mi][ni4 * 2],     ah[mi], bh[0], bh[1]);
                    mma_f16(acc[mi][ni4 * 2 + 1], ah[mi], bh[2], bh[3]);
                    mma_f16(acc[mi][ni4 * 2],     al[mi], bh[0], bh[1]);
                    mma_f16(acc[mi][ni4 * 2 + 1], al[mi], bh[2], bh[3]);
                }
            }
        }
        __syncthreads();
    }

    // ---- epilogue ----
    int gr = lane >> 2, tg = lane & 3;

    if (fuseFinal) {
        float p[4] = {0.f, 0.f, 0.f, 0.f};
#pragma unroll
        for (int mi = 0; mi < 2; mi++) {
            int ra = wm + mi * 16 + gr;
            int rb = ra + 8;
            int ia = sIdx[ra], ib = sIdx[rb];
#pragma unroll
            for (int ni = 0; ni < 8; ni++) {
                int col = wn + ni * 8 + tg * 2;
                const float* bp = biasL + (long)a * sBias + col;
                float b0 = bp[0], b1 = bp[1];
                float v0 = acc[mi][ni][0] + b0;
                float v1 = acc[mi][ni][1] + b1;
                float v2 = acc[mi][ni][2] + b0;
                float v3 = acc[mi][ni][3] + b1;
                v0 = v0 > 0.f ? v0 : 0.01f * v0;
                v1 = v1 > 0.f ? v1 : 0.01f * v1;
                v2 = v2 > 0.f ? v2 : 0.01f * v2;
                v3 = v3 > 0.f ? v3 : 0.01f * v3;
                p[mi * 2]     += v0 * sWc2[col * ACT + ia] + v1 * sWc2[(col + 1) * ACT + ia];
                p[mi * 2 + 1] += v2 * sWc2[col * ACT + ib] + v3 * sWc2[(col + 1) * ACT + ib];
            }
        }
#pragma unroll
        for (int q = 0; q < 4; q++) {
            p[q] += __shfl_xor_sync(0xffffffffu, p[q], 1);
            p[q] += __shfl_xor_sync(0xffffffffu, p[q], 2);
        }
        int nh = wid >> 2;
        if (tg == 0) {
            sQred[nh][wm + gr]      = p[0];
            sQred[nh][wm + gr + 8]  = p[1];
            sQred[nh][wm + gr + 16] = p[2];
            sQred[nh][wm + gr + 24] = p[3];
        }
        __syncthreads();
        if (tid < 128) {
            float q = sQred[0][tid] + sQred[1][tid] + bc2[a * ACT + sIdx[tid]];
            outq[(long)a * BATCH + mBase + tid] = q;
        }
        return;
    }

#pragma unroll
    for (int mi = 0; mi < 2; mi++) {
        long row0 = mBase + wm + mi * 16 + gr;
        long row1 = row0 + 8;
#pragma unroll
        for (int ni = 0; ni < 8; ni++) {
            int col = colBase + wn + ni * 8 + tg * 2;
            float b0 = 0.f, b1 = 0.f;
            if (biasL) {
                const float* bp = biasL + (long)a * sBias + col;
                b0 = bp[0]; b1 = bp[1];
            }
            float v0 = acc[mi][ni][0] + b0;
            float v1 = acc[mi][ni][1] + b1;
            float v2 = acc[mi][ni][2] + b0;
            float v3 = acc[mi][ni][3] + b1;
            if (col >= actF) {
                v0 = v0 > 0.f ? v0 : 0.01f * v0;
                v2 = v2 > 0.f ? v2 : 0.01f * v2;
            }
            if (col + 1 >= actF) {
                v1 = v1 > 0.f ? v1 : 0.01f * v1;
                v3 = v3 > 0.f ? v3 : 0.01f * v3;
            }
            if (outHalf) {
                long o0 = (long)a * sCout + row0 * ldcL + col;
                long o1 = (long)a * sCout + row1 * ldcL + col;
                __half h0 = __float2half_rn(v0), h1 = __float2half_rn(v1);
                __half h2 = __float2half_rn(v2), h3 = __float2half_rn(v3);
                *(uint32_t*)(Ch + o0) = (uint32_t)__half_as_ushort(h0) |
                                        ((uint32_t)__half_as_ushort(h1) << 16);
                *(uint32_t*)(Ch + o1) = (uint32_t)__half_as_ushort(h2) |
                                        ((uint32_t)__half_as_ushort(h3) << 16);
                *(uint32_t*)(Cl + o0) = pack_h2(v0 - __half2float(h0), v1 - __half2float(h1));
                *(uint32_t*)(Cl + o1) = pack_h2(v2 - __half2float(h2), v3 - __half2float(h3));
            } else {
                float* Cp = Cout + (long)a * sCout;
                *(float2*)(Cp + row0 * ldcL + col) = make_float2(v0, v1);
                *(float2*)(Cp + row1 * ldcL + col) = make_float2(v2, v3);
            }
        }
    }
}

// ---------------- attention: one warp per (head, agent_i, batch) --------------
__global__ void attn_kernel(const float* __restrict__ KV, const float* __restrict__ St,
                            __half* __restrict__ oH, __half* __restrict__ oL)
{
    int gw   = blockIdx.x * 8 + (threadIdx.x >> 5);
    int lane = threadIdx.x & 31;
    int b = gw >> 6;
    int r = gw & 63;
    int n = r >> 4;
    int i = r & 15;
    int col = n * DHEAD + lane;

    float selv = St[((long)i * BATCH + b) * HID + col];
    float lg = -3e38f;
#pragma unroll
    for (int j = 0; j < 16; j++) {
        float p = selv * KV[((long)j * BATCH + b) * 256 + col];
#pragma unroll
        for (int off = 16; off; off >>= 1) p += __shfl_xor_sync(0xffffffffu, p, off);
        if (lane == j) lg = (j == i) ? -1e9f : p * 0.17677669529663687f;
    }
    float mx = lg;
#pragma unroll
    for (int off = 16; off; off >>= 1) mx = fmaxf(mx, __shfl_xor_sync(0xffffffffu, mx, off));
    float e = (lane < 16) ? __expf(lg - mx) : 0.f;
    float den = e;
#pragma unroll
    for (int off = 16; off; off >>= 1) den += __shfl_xor_sync(0xffffffffu, den, off);
    float w = e / den;

    float acc = 0.f;
#pragma unroll
    for (int j = 0; j < 16; j++) {
        float wj = __shfl_sync(0xffffffffu, w, j);
        acc = fmaf(wj, KV[((long)j * BATCH + b) * 256 + 128 + col], acc);
    }
    long o = ((long)i * BATCH + b) * HID + col;
    __half h = __float2half_rn(acc);
    oH[o] = h;
    oL[o] = __float2half_rn(acc - __half2float(h));
}

// ---------------- launch -------------------------------------------------------
static float* symaddr(const void* sym)
{
    void* p = nullptr;
    cudaGetSymbolAddress(&p, sym);
    return (float*)p;
}
static __half* symaddr_h(const void* sym)
{
    void* p = nullptr;
    cudaGetSymbolAddress(&p, sym);
    return (__half*)p;
}

extern "C" void kernel_launch(void* const* d_in, const int* in_sizes, int n_in,
                              void* d_out, int out_size)
{
    const float* obs     = (const float*)d_in[0];
    const float* actions = (const float*)d_in[1];
    const float* W_sa    = (const float*)d_in[2];
    const float* b_sa    = (const float*)d_in[3];
    const float* W_s     = (const float*)d_in[4];
    const float* b_s     = (const float*)d_in[5];
    const float* Wk      = (const float*)d_in[6];
    const float* Wsel    = (const float*)d_in[7];
    const float* Wv      = (const float*)d_in[8];
    const float* bv      = (const float*)d_in[9];
    const float* Wc1     = (const float*)d_in[10];
    const float* bc1     = (const float*)d_in[11];
    const float* Wc2     = (const float*)d_in[12];
    const float* bc2     = (const float*)d_in[13];
    float* out = (float*)d_out;

    float* ps    = symaddr(g_ps);
    float* ps2   = symaddr(g_ps2);
    float* mean  = symaddr(g_mean);
    float* istd  = symaddr(g_istd);
    float* b1    = symaddr(g_b1);
    float* bkv   = symaddr(g_bkv);
    float* KV    = symaddr(g_KV);
    float* St    = symaddr(g_S);

    __half* w1h  = symaddr_h(w1_h);
    __half* kvh  = symaddr_h(wkv_h);
    __half* selh = symaddr_h(wsel_h);
    __half* c1h  = symaddr_h(wc1_h);
    __half* obsH = symaddr_h(g_obsH);
    __half* obsL = symaddr_h(g_obsL);
    __half* actH = symaddr_h(g_actH);
    __half* actL = symaddr_h(g_actL);
    __half* aseH = symaddr_h(g_aseH);
    __half* aseL = symaddr_h(g_aseL);
    __half* othH = symaddr_h(g_othH);
    __half* othL = symaddr_h(g_othL);

    static bool attr_set = false;
    if (!attr_set) {
        cudaFuncSetAttribute(gemm_mma, cudaFuncAttributeMaxDynamicSharedMemorySize,
                             3 * 2 * PLANE * 2);
        attr_set = true;
    }

    const long sOBS = (long)BATCH * OBS;
    const long sACT = (long)BATCH * ACT;
    const long sASE = (long)BATCH * 256;
    const long sH   = (long)BATCH * HID;
    size_t smem = 3 * 2 * PLANE * 2;   // 61440

    // launch index: 0
    bn_part_kernel<<<dim3(AGENTS, 5, 8), dim3(32, 32)>>>(obs, actions, ps, ps2,
                                                          obsH, obsL, actH, actL);
    // 1
    bn_fin_kernel<<<AGENTS, 160>>>(ps, ps2, mean, istd);
    // 2
    prep_all<<<dim3(160, 5, AGENTS), 256>>>(W_sa, b_sa, W_s, b_s, Wk, Wsel, Wv, bv,
                                            Wc1, mean, istd,
                                            w1h, kvh, selh, c1h, b1, bkv);

    // 3 (capture target): ase = lrelu(bn([obs|act]) @ [W_sa|W_s] + b1)  K=144->160
    gemm_mma<<<dim3(BATCH / 128, 2, AGENTS), 256, smem>>>(
        obsH, obsL, sOBS, OBS, actH, actL, sACT, ACT, OBS, INP,
        w1h, (long)256 * 160, 160,
        b1, 256, nullptr, sASE, 256, 0,
        1, aseH, aseL,
        0, nullptr, nullptr, 0,
        0, nullptr, nullptr, nullptr, nullptr);

    // 4: merged KV + Sel.  y<2: KV = sa @ [Wk|Wv]; y==2: S = se @ Wsel
    gemm_mma<<<dim3(BATCH / 128, 3, AGENTS), 256, smem>>>(
        aseH, aseL, sASE, 256, aseH, aseL, 0, 0, 1 << 30, HID,
        kvh, 0, HID,
        bkv, 0, KV, sASE, 256, 128,
        0, nullptr, nullptr,
        1, selh, St, sH,
        0, nullptr, nullptr, nullptr, nullptr);

    // 5: attention -> other (fp16 pair)
    attn_kernel<<<(BATCH * 64) / 8, 256>>>(KV, St, othH, othL);

    // 6: q = fused( lrelu([se|other] @ Wc1 + bc1) . Wc2[:,argmax] + bc2 )  K=256
    gemm_mma<<<dim3(BATCH / 128, 1, AGENTS), 256, smem>>>(
        aseH + 128, aseL + 128, sASE, 256, othH, othL, sH, HID, HID, 2 * HID,
        c1h, (long)HID * 2 * HID, 2 * HID,
        bc1, HID, nullptr, 0, 0, 1 << 30,
        0, nullptr, nullptr,
        0, nullptr, nullptr, 0,
        1, actions, Wc2, bc2, out);
}